// round 8
// baseline (speedup 1.0000x reference)
#include <cuda_runtime.h>
#include <cuda_bf16.h>
#include <math.h>
#include <stdint.h>

namespace {
constexpr int Bc  = 2;
constexpr int Sc  = 2048;
constexpr int Hc  = 4096;
constexpr int NHc = 32;
constexpr int HDc = 128;
constexpr int Ic  = 11008;
constexpr int Tc  = Bc * Sc;
constexpr int HALFc = HDc / 2;
constexpr float EPSc = 1e-6f;
constexpr float SCALEc = 0.08838834764831843f;
}

// ---------------- device scratch ----------------
__device__ float g_res1  [(size_t)Tc * Hc];
__device__ float g_qkv   [(size_t)Tc * 3 * Hc];     // qkv fp32; later reused for act fp32
__device__ float g_scores[(size_t)Bc * NHc * Sc * Sc]; // scores fp32; later attn fp32 [T,H]
__device__ float g_gu    [(size_t)Tc * 2 * Ic];

__device__ __nv_bfloat16 g_q_hi [(size_t)Tc * Hc],  g_q_lo [(size_t)Tc * Hc];
__device__ __nv_bfloat16 g_k_hi [(size_t)Tc * Hc],  g_k_lo [(size_t)Tc * Hc];
__device__ __nv_bfloat16 g_vt_hi[(size_t)Tc * Hc],  g_vt_lo[(size_t)Tc * Hc];
__device__ __nv_bfloat16 g_p_hi [(size_t)Bc * NHc * Sc * Sc];
__device__ __nv_bfloat16 g_p_lo [(size_t)Bc * NHc * Sc * Sc];

__device__ signed char g_n_q1 [(size_t)Tc * Hc], g_n_q2 [(size_t)Tc * Hc];
__device__ float       g_n_s  [Tc];
__device__ signed char g_at_q1[(size_t)Tc * Hc], g_at_q2[(size_t)Tc * Hc];
__device__ float       g_at_s [Tc];
__device__ signed char g_ac_q1[(size_t)Tc * Ic], g_ac_q2[(size_t)Tc * Ic];
__device__ float       g_ac_s [Tc];
__device__ signed char g_wqkv_q1[(size_t)3 * Hc * Hc], g_wqkv_q2[(size_t)3 * Hc * Hc];
__device__ float       g_wqkv_s[3 * Hc];
__device__ signed char g_wo_q1 [(size_t)Hc * Hc], g_wo_q2 [(size_t)Hc * Hc];
__device__ float       g_wo_s  [Hc];
__device__ signed char g_wgu_q1[(size_t)2 * Ic * Hc], g_wgu_q2[(size_t)2 * Ic * Hc];
__device__ float       g_wgu_s [2 * Ic];
__device__ signed char g_wdn_q1[(size_t)Hc * Ic], g_wdn_q2[(size_t)Hc * Ic];
__device__ float       g_wdn_s [Hc];

// ---------------- helpers ----------------
__device__ __forceinline__ uint32_t smem_u32(const void* p) {
    return (uint32_t)__cvta_generic_to_shared(p);
}
__device__ __forceinline__ void ldsm_x4(uint32_t (&r)[4], uint32_t addr) {
    asm volatile("ldmatrix.sync.aligned.m8n8.x4.shared.b16 {%0,%1,%2,%3}, [%4];"
                 : "=r"(r[0]), "=r"(r[1]), "=r"(r[2]), "=r"(r[3]) : "r"(addr));
}
__device__ __forceinline__ void mma_bf16(float (&d)[4], const uint32_t (&a)[4],
                                         uint32_t b0, uint32_t b1) {
    asm volatile("mma.sync.aligned.m16n8k16.row.col.f32.bf16.bf16.f32 "
        "{%0,%1,%2,%3}, {%4,%5,%6,%7}, {%8,%9}, {%0,%1,%2,%3};"
        : "+f"(d[0]), "+f"(d[1]), "+f"(d[2]), "+f"(d[3])
        : "r"(a[0]), "r"(a[1]), "r"(a[2]), "r"(a[3]), "r"(b0), "r"(b1));
}
__device__ __forceinline__ void mma_s8(int (&d)[4], const uint32_t (&a)[4],
                                       uint32_t b0, uint32_t b1) {
    asm volatile("mma.sync.aligned.m16n8k32.row.col.s32.s8.s8.s32 "
        "{%0,%1,%2,%3}, {%4,%5,%6,%7}, {%8,%9}, {%0,%1,%2,%3};"
        : "+r"(d[0]), "+r"(d[1]), "+r"(d[2]), "+r"(d[3])
        : "r"(a[0]), "r"(a[1]), "r"(a[2]), "r"(a[3]), "r"(b0), "r"(b1));
}
__device__ __forceinline__ void cp_async16(uint32_t dst, const void* src) {
    asm volatile("cp.async.cg.shared.global [%0], [%1], 16;" :: "r"(dst), "l"(src));
}
#define CP_COMMIT() asm volatile("cp.async.commit_group;" ::: "memory")
#define CP_WAIT(n)  asm volatile("cp.async.wait_group %0;" :: "n"(n) : "memory")
__device__ __forceinline__ void split2(float v, __nv_bfloat16& h, __nv_bfloat16& l) {
    h = __float2bfloat16(v);
    l = __float2bfloat16(v - __bfloat162float(h));
}
__device__ __forceinline__ void quant2(float v, float inv, signed char& a, signed char& b) {
    float t = v * inv;
    float r1 = rintf(t);
    a = (signed char)(int)r1;
    b = (signed char)(int)rintf((t - r1) * 128.f);
}

__device__ __forceinline__ float block_reduce_sum_256(float v) {
    #pragma unroll
    for (int o = 16; o > 0; o >>= 1) v += __shfl_down_sync(0xffffffffu, v, o);
    __shared__ float red[8];
    int w = threadIdx.x >> 5, l = threadIdx.x & 31;
    if (l == 0) red[w] = v;
    __syncthreads();
    if (w == 0) {
        float x = (l < 8) ? red[l] : 0.f;
        #pragma unroll
        for (int o = 4; o > 0; o >>= 1) x += __shfl_down_sync(0xffu, x, o);
        if (l == 0) red[0] = x;
    }
    __syncthreads();
    float r = red[0];
    __syncthreads();
    return r;
}
__device__ __forceinline__ float block_reduce_max_256(float v) {
    #pragma unroll
    for (int o = 16; o > 0; o >>= 1) v = fmaxf(v, __shfl_down_sync(0xffffffffu, v, o));
    __shared__ float red[8];
    int w = threadIdx.x >> 5, l = threadIdx.x & 31;
    if (l == 0) red[w] = v;
    __syncthreads();
    if (w == 0) {
        float x = (l < 8) ? red[l] : -INFINITY;
        #pragma unroll
        for (int o = 4; o > 0; o >>= 1) x = fmaxf(x, __shfl_down_sync(0xffu, x, o));
        if (l == 0) red[0] = x;
    }
    __syncthreads();
    float r = red[0];
    __syncthreads();
    return r;
}

// ---------------- add + RMSNorm -> int8 2-plane ----------------
__global__ __launch_bounds__(256) void add_rmsnorm_q_kernel(
    const float* __restrict__ a, const float* __restrict__ b,
    const float* __restrict__ w, float* __restrict__ sum_out,
    signed char* __restrict__ q1, signed char* __restrict__ q2,
    float* __restrict__ scl)
{
    int row = blockIdx.x;
    const float4* a4 = (const float4*)(a + (size_t)row * Hc);
    const float4* b4 = b ? (const float4*)(b + (size_t)row * Hc) : nullptr;
    const float4* w4 = (const float4*)w;
    float4* s4 = sum_out ? (float4*)(sum_out + (size_t)row * Hc) : nullptr;

    float4 v[4];
    float ss = 0.f;
    #pragma unroll
    for (int it = 0; it < 4; it++) {
        int idx = threadIdx.x + it * 256;
        float4 va = a4[idx];
        if (b4) { float4 vb = b4[idx]; va.x += vb.x; va.y += vb.y; va.z += vb.z; va.w += vb.w; }
        v[it] = va;
        ss += va.x * va.x + va.y * va.y + va.z * va.z + va.w * va.w;
    }
    float tot = block_reduce_sum_256(ss);
    float rs = rsqrtf(tot / (float)Hc + EPSc);

    float y[16];
    float mx = 0.f;
    #pragma unroll
    for (int it = 0; it < 4; it++) {
        int idx = threadIdx.x + it * 256;
        if (s4) s4[idx] = v[it];
        float4 vw = w4[idx];
        y[it*4+0] = v[it].x * rs * vw.x;  y[it*4+1] = v[it].y * rs * vw.y;
        y[it*4+2] = v[it].z * rs * vw.z;  y[it*4+3] = v[it].w * rs * vw.w;
        mx = fmaxf(mx, fmaxf(fmaxf(fabsf(y[it*4]), fabsf(y[it*4+1])),
                             fmaxf(fabsf(y[it*4+2]), fabsf(y[it*4+3]))));
    }
    float rmx = block_reduce_max_256(mx);
    float inv = rmx > 0.f ? 127.f / rmx : 0.f;
    if (threadIdx.x == 0) scl[row] = rmx / 127.f;
    #pragma unroll
    for (int it = 0; it < 4; it++) {
        int idx = threadIdx.x + it * 256;
        char4 c1, c2;
        quant2(y[it*4+0], inv, c1.x, c2.x);
        quant2(y[it*4+1], inv, c1.y, c2.y);
        quant2(y[it*4+2], inv, c1.z, c2.z);
        quant2(y[it*4+3], inv, c1.w, c2.w);
        *(char4*)(q1 + (size_t)row * Hc + idx * 4) = c1;
        *(char4*)(q2 + (size_t)row * Hc + idx * 4) = c2;
    }
}

// ---------------- generic fp32 row -> int8 2-plane ----------------
__global__ __launch_bounds__(256) void row_quant_kernel(
    const float* __restrict__ X, int K,
    signed char* __restrict__ q1, signed char* __restrict__ q2,
    float* __restrict__ scl)
{
    int row = blockIdx.x;
    const float* x = X + (size_t)row * K;
    float mx = 0.f;
    for (int j = threadIdx.x; j < K; j += 256) mx = fmaxf(mx, fabsf(x[j]));
    float rmx = block_reduce_max_256(mx);
    float inv = rmx > 0.f ? 127.f / rmx : 0.f;
    if (threadIdx.x == 0) scl[row] = rmx / 127.f;
    for (int j = threadIdx.x; j < K; j += 256) {
        signed char a, b;
        quant2(x[j], inv, a, b);
        q1[(size_t)row * K + j] = a;
        q2[(size_t)row * K + j] = b;
    }
}

// ---------------- per-column |max| of W[K,N] ----------------
__global__ __launch_bounds__(256) void colmax_kernel(
    const float* __restrict__ W, int K, int N, float* __restrict__ scl)
{
    int n = blockIdx.x * 256 + threadIdx.x;
    float mx = 0.f;
    for (int k = 0; k < K; k++) mx = fmaxf(mx, fabsf(W[(size_t)k * N + n]));
    scl[n] = mx / 127.f;
}

// ---------------- transpose+quant: W[K,N] -> q planes [N,K] ----------------
__global__ __launch_bounds__(256) void transpose_quant_kernel(
    const float* __restrict__ in, int in_ld,
    signed char* __restrict__ q1, signed char* __restrict__ q2,
    const float* __restrict__ scl, int K)
{
    __shared__ float tile[32][33];
    int tx = threadIdx.x & 31, ty = threadIdx.x >> 5;
    int gx = blockIdx.x * 32 + tx;
    #pragma unroll
    for (int i = 0; i < 4; i++) {
        int gy = blockIdx.y * 32 + ty + i * 8;
        tile[ty + i * 8][tx] = in[(size_t)gy * in_ld + gx];
    }
    __syncthreads();
    int ox = blockIdx.y * 32 + tx;
    #pragma unroll
    for (int i = 0; i < 4; i++) {
        int oy = blockIdx.x * 32 + ty + i * 8;
        float s = scl[oy];
        float inv = s > 0.f ? 1.f / s : 0.f;
        signed char a, b;
        quant2(tile[tx][ty + i * 8], inv, a, b);
        q1[(size_t)oy * K + ox] = a;
        q2[(size_t)oy * K + ox] = b;
    }
}

// ---------------- V transpose -> bf16 hi/lo [z][HD][S] ----------------
__global__ __launch_bounds__(256) void transpose_convert_kernel(
    const float* __restrict__ in, long long inSb, long long inSh, int in_ld,
    __nv_bfloat16* __restrict__ ohi, __nv_bfloat16* __restrict__ olo,
    long long outSz, int Y)
{
    __shared__ float tile[32][33];
    int z = blockIdx.z, zb = z / NHc, zh = z % NHc;
    const float* inp = in + zb * inSb + zh * inSh;
    __nv_bfloat16* oh = ohi + (long long)z * outSz;
    __nv_bfloat16* ol = olo + (long long)z * outSz;
    int tx = threadIdx.x & 31, ty = threadIdx.x >> 5;
    int gx = blockIdx.x * 32 + tx;
    #pragma unroll
    for (int i = 0; i < 4; i++) {
        int gy = blockIdx.y * 32 + ty + i * 8;
        tile[ty + i * 8][tx] = inp[(size_t)gy * in_ld + gx];
    }
    __syncthreads();
    int ox = blockIdx.y * 32 + tx;
    #pragma unroll
    for (int i = 0; i < 4; i++) {
        int oy = blockIdx.x * 32 + ty + i * 8;
        __nv_bfloat16 h, l;
        split2(tile[tx][ty + i * 8], h, l);
        oh[(size_t)oy * Y + ox] = h;
        ol[(size_t)oy * Y + ox] = l;
    }
}

// ---------------- RoPE -> Q/K bf16 hi/lo ----------------
__global__ __launch_bounds__(256) void rope_kernel(
    const float* __restrict__ qkv, const float* __restrict__ cosp,
    const float* __restrict__ sinp,
    __nv_bfloat16* __restrict__ qhi, __nv_bfloat16* __restrict__ qlo,
    __nv_bfloat16* __restrict__ khi, __nv_bfloat16* __restrict__ klo)
{
    int idx = blockIdx.x * 256 + threadIdx.x;
    int d = idx & (HALFc - 1);
    int h = (idx >> 6) & (NHc - 1);
    int m = (idx >> 11) & 1;
    int t = idx >> 12;
    const float* p = qkv + (size_t)t * (3 * Hc) + m * Hc + h * HDc + d;
    float x1 = p[0], x2 = p[HALFc];
    float c = cosp[(size_t)t * HALFc + d];
    float s = sinp[(size_t)t * HALFc + d];
    float y1 = x1 * c - x2 * s;
    float y2 = x1 * s + x2 * c;
    __nv_bfloat16* dh = (m ? khi : qhi) + (size_t)t * Hc + h * HDc + d;
    __nv_bfloat16* dl = (m ? klo : qlo) + (size_t)t * Hc + h * HDc + d;
    __nv_bfloat16 h1, l1, h2, l2;
    split2(y1, h1, l1); split2(y2, h2, l2);
    dh[0] = h1; dh[HALFc] = h2;
    dl[0] = l1; dl[HALFc] = l2;
}

// ---------------- causal softmax -> P bf16 hi/lo ----------------
__global__ __launch_bounds__(256) void softmax_kernel(
    const float* __restrict__ scores,
    __nv_bfloat16* __restrict__ phi, __nv_bfloat16* __restrict__ plo)
{
    int i = blockIdx.x;
    int z = blockIdx.y;
    const float* row = scores + (size_t)z * Sc * Sc + (size_t)i * Sc;
    __nv_bfloat16* ph = phi + (size_t)z * Sc * Sc + (size_t)i * Sc;
    __nv_bfloat16* pl = plo + (size_t)z * Sc * Sc + (size_t)i * Sc;
    int nvalid = i + 1;

    float vals[8];
    float mx = -INFINITY;
    #pragma unroll
    for (int it = 0; it < 8; it++) {
        int j = threadIdx.x + it * 256;
        float v = (j < nvalid) ? row[j] : -INFINITY;
        vals[it] = v;
        mx = fmaxf(mx, v);
    }
    float M = block_reduce_max_256(mx);
    float sum = 0.f;
    #pragma unroll
    for (int it = 0; it < 8; it++) {
        int j = threadIdx.x + it * 256;
        float e = (j < nvalid) ? __expf(vals[it] - M) : 0.f;
        vals[it] = e;
        sum += e;
    }
    float tot = block_reduce_sum_256(sum);
    float inv = 1.f / tot;
    int zero_end = ((i >> 8) + 1) << 8;
    #pragma unroll
    for (int it = 0; it < 8; it++) {
        int j = threadIdx.x + it * 256;
        if (j < zero_end) {
            __nv_bfloat16 h, l;
            split2(vals[it] * inv, h, l);
            ph[j] = h; pl[j] = l;
        }
    }
}

// ---------------- SiLU(gate)*up -> fp32 ----------------
__global__ __launch_bounds__(256) void silu_fp32_kernel(
    const float* __restrict__ gu, float* __restrict__ act)
{
    int t = blockIdx.y;
    int i = blockIdx.x * 256 + threadIdx.x;
    float g = gu[(size_t)t * (2 * Ic) + i];
    float u = gu[(size_t)t * (2 * Ic) + Ic + i];
    act[(size_t)t * Ic + i] = g / (1.f + __expf(-g)) * u;
}

// ==================================================================
// bf16 GEMM (attention): C = alpha*(A@B^T). BM=256,BN=128,BK=32,
// 8 warps 64x64, cp.async 2-stage, 3 passes. fp32 out.
// ==================================================================
namespace gk {
constexpr int BM = 256, BN = 128, BK = 32, SROW = 40;
constexpr int AOFF_L = BM * SROW * 2;
constexpr int BOFF_H = 2 * AOFF_L;
constexpr int BOFF_L = BOFF_H + BN * SROW * 2;
constexpr int STAGE  = BOFF_L + BN * SROW * 2;
constexpr int SMEM_SZ = 2 * STAGE;
}

template<bool CAUSAL, bool KLIM>
__global__ __launch_bounds__(256, 1) void hmma_gemm_kernel(
    const __nv_bfloat16* __restrict__ Ahi, const __nv_bfloat16* __restrict__ Alo,
    const __nv_bfloat16* __restrict__ Bhi, const __nv_bfloat16* __restrict__ Blo,
    float* __restrict__ Cf,
    int K, int lda, int ldb, int ldc,
    long long sAb, long long sAh_, long long sBb, long long sBh_,
    long long sCb, long long sCh_, float alpha)
{
    using namespace gk;
    int rowBase = blockIdx.y * BM;
    int colBase = blockIdx.x * BN;
    if (CAUSAL && colBase > rowBase + BM - 1) return;

    extern __shared__ char smraw[];
    uint32_t sbase = smem_u32(smraw);

    int tid = threadIdx.x;
    int wid = tid >> 5, lane = tid & 31;
    int wm = wid & 3, wn = wid >> 2;

    int z = blockIdx.z, zb = z / NHc, zh = z % NHc;
    const __nv_bfloat16* Ah = Ahi + zb * sAb + zh * sAh_;
    const __nv_bfloat16* Al = Alo + zb * sAb + zh * sAh_;
    const __nv_bfloat16* Bh = Bhi + zb * sBb + zh * sBh_;
    const __nv_bfloat16* Bl = Blo + zb * sBb + zh * sBh_;

    int kEnd = KLIM ? min(K, rowBase + BM) : K;
    int nch  = kEnd / BK;

    float acc[4][8][4];
    #pragma unroll
    for (int a = 0; a < 4; a++)
        #pragma unroll
        for (int b = 0; b < 8; b++)
            #pragma unroll
            for (int c = 0; c < 4; c++) acc[a][b][c] = 0.f;

    int ar = tid >> 2, sg = (tid & 3) * 8;
    uint32_t soff = (uint32_t)(ar * SROW + sg) * 2;

    auto issue = [&](int c, int s) {
        int k0 = c * BK;
        uint32_t st = sbase + s * STAGE;
        #pragma unroll
        for (int it = 0; it < 4; it++) {
            int r = ar + it * 64;
            uint32_t o = soff + (uint32_t)(it * 64 * SROW) * 2;
            cp_async16(st + o,          Ah + (size_t)(rowBase + r) * lda + k0 + sg);
            cp_async16(st + AOFF_L + o, Al + (size_t)(rowBase + r) * lda + k0 + sg);
        }
        #pragma unroll
        for (int it = 0; it < 2; it++) {
            int r = ar + it * 64;
            uint32_t o = soff + (uint32_t)(it * 64 * SROW) * 2;
            cp_async16(st + BOFF_H + o, Bh + (size_t)(colBase + r) * ldb + k0 + sg);
            cp_async16(st + BOFF_L + o, Bl + (size_t)(colBase + r) * ldb + k0 + sg);
        }
    };

    int mat = lane >> 3, r8 = lane & 7;
    int a_row = (mat & 1) * 8 + r8, a_k = (mat >> 1) * 8;
    int b_n   = (mat >> 1) * 8 + r8, b_k = (mat & 1) * 8;

    issue(0, 0); CP_COMMIT();

    for (int c = 0; c < nch; ++c) {
        if (c + 1 < nch) { issue(c + 1, (c + 1) & 1); CP_COMMIT(); CP_WAIT(1); }
        else             { CP_WAIT(0); }
        __syncthreads();

        uint32_t st = sbase + (c & 1) * STAGE;
        #pragma unroll
        for (int ks = 0; ks < 2; ++ks) {
            uint32_t ah[4][4], al[4][4];
            #pragma unroll
            for (int mt = 0; mt < 4; ++mt) {
                uint32_t off = (uint32_t)((wm * 64 + mt * 16 + a_row) * SROW
                                          + ks * 16 + a_k) * 2;
                ldsm_x4(ah[mt], st + off);
                ldsm_x4(al[mt], st + AOFF_L + off);
            }
            #pragma unroll
            for (int nt = 0; nt < 4; ++nt) {
                uint32_t boff = (uint32_t)((wn * 64 + nt * 16 + b_n) * SROW
                                           + ks * 16 + b_k) * 2;
                uint32_t bh[4], bl[4];
                ldsm_x4(bh, st + BOFF_H + boff);
                ldsm_x4(bl, st + BOFF_L + boff);
                #pragma unroll
                for (int mt = 0; mt < 4; ++mt) {
                    #pragma unroll
                    for (int h2 = 0; h2 < 2; ++h2) {
                        mma_bf16(acc[mt][nt*2+h2], ah[mt], bh[2*h2], bh[2*h2+1]);
                        mma_bf16(acc[mt][nt*2+h2], ah[mt], bl[2*h2], bl[2*h2+1]);
                        mma_bf16(acc[mt][nt*2+h2], al[mt], bh[2*h2], bh[2*h2+1]);
                    }
                }
            }
        }
        __syncthreads();
    }

    float* Cfz = Cf + zb * sCb + zh * sCh_;
    #pragma unroll
    for (int mt = 0; mt < 4; ++mt) {
        int r = rowBase + wm * 64 + mt * 16 + (lane >> 2);
        #pragma unroll
        for (int j8 = 0; j8 < 8; ++j8) {
            int cc = colBase + wn * 64 + j8 * 8 + 2 * (lane & 3);
            *(float2*)(Cfz + (size_t)r * ldc + cc) =
                make_float2(acc[mt][j8][0] * alpha, acc[mt][j8][1] * alpha);
            *(float2*)(Cfz + (size_t)(r + 8) * ldc + cc) =
                make_float2(acc[mt][j8][2] * alpha, acc[mt][j8][3] * alpha);
        }
    }
}

// ==================================================================
// s8 GEMM (weights): C = sA[m]*sB[n]*(q1q1 + (q1q2+q2q1)/128) [+ADD]
// BM=BN=128, BK=64(s8), 8 warps 32x64 tiles, cp.async 2-stage.
// ==================================================================
namespace qk8 {
constexpr int BM = 128, BN = 128, BK = 64, SROWB = 80;
constexpr int PB = BM * SROWB;            // 10240
constexpr int STAGE = 4 * PB;             // 40960
constexpr int SMEM_SZ = 2 * STAGE;        // 81920
}

template<bool ADDC>
__global__ __launch_bounds__(256, 1) void s8_gemm_kernel(
    const signed char* __restrict__ Aq1, const signed char* __restrict__ Aq2,
    const float* __restrict__ sA,
    const signed char* __restrict__ Bq1, const signed char* __restrict__ Bq2,
    const float* __restrict__ sB,
    float* __restrict__ C, const float* __restrict__ ADD,
    int K, int ldc)
{
    using namespace qk8;
    int rowBase = blockIdx.y * BM;
    int colBase = blockIdx.x * BN;

    extern __shared__ char smraw[];
    uint32_t sbase = smem_u32(smraw);

    int tid = threadIdx.x;
    int wid = tid >> 5, lane = tid & 31;
    int wm = wid & 3, wn = wid >> 2;          // warp tile 32m x 64n

    int nch = K / BK;

    int accP[2][8][4], accC[2][8][4];
    #pragma unroll
    for (int a = 0; a < 2; a++)
        #pragma unroll
        for (int b = 0; b < 8; b++)
            #pragma unroll
            for (int c = 0; c < 4; c++) { accP[a][b][c] = 0; accC[a][b][c] = 0; }

    int ar = tid >> 2, sg = (tid & 3) * 16;       // 128 rows x 4 segs of 16B
    uint32_t soff = (uint32_t)(ar * SROWB + sg);

    auto issue = [&](int c, int s) {
        int k0 = c * BK;
        uint32_t st = sbase + s * STAGE;
        #pragma unroll
        for (int it = 0; it < 2; it++) {
            int r = ar + it * 64;
            uint32_t o = soff + (uint32_t)(it * 64 * SROWB);
            cp_async16(st + o,          Aq1 + (size_t)(rowBase + r) * K + k0 + sg);
            cp_async16(st + PB + o,     Aq2 + (size_t)(rowBase + r) * K + k0 + sg);
            cp_async16(st + 2*PB + o,   Bq1 + (size_t)(colBase + r) * K + k0 + sg);
            cp_async16(st + 3*PB + o,   Bq2 + (size_t)(colBase + r) * K + k0 + sg);
        }
    };

    int mat = lane >> 3, r8 = lane & 7;
    int a_row = (mat & 1) * 8 + r8, a_k = (mat >> 1) * 8;   // b16 units
    int b_n   = (mat >> 1) * 8 + r8, b_k = (mat & 1) * 8;

    issue(0, 0); CP_COMMIT();

    for (int c = 0; c < nch; ++c) {
        if (c + 1 < nch) { issue(c + 1, (c + 1) & 1); CP_COMMIT(); CP_WAIT(1); }
        else             { CP_WAIT(0); }
        __syncthreads();

        uint32_t st = sbase + (c & 1) * STAGE;
        #pragma unroll
        for (int ks = 0; ks < 2; ++ks) {          // each ks = 32 s8 of K
            uint32_t a1[2][4], a2[2][4];
            #pragma unroll
            for (int mt = 0; mt < 2; ++mt) {
                uint32_t off = (uint32_t)((wm * 32 + mt * 16 + a_row) * SROWB
                                          + (ks * 16 + a_k) * 2);
                ldsm_x4(a1[mt], st + off);
                ldsm_x4(a2[mt], st + PB + off);
            }
            #pragma unroll
            for (int nt = 0; nt < 4; ++nt) {
                uint32_t boff = (uint32_t)((wn * 64 + nt * 16 + b_n) * SROWB
                                           + (ks * 16 + b_k) * 2);
                uint32_t b1[4], b2[4];
                ldsm_x4(b1, st + 2*PB + boff);
                ldsm_x4(b2, st + 3*PB + boff);
                #pragma unroll
                for (int mt = 0; mt < 2; ++mt) {
                    #pragma unroll
                    for (int h2 = 0; h2 < 2; ++h2) {
                        mma_s8(accP[mt][nt*2+h2], a1[mt], b1[2*h2], b1[2*h2+1]);
                        mma_s8(accC[mt][nt*2+h2], a1[mt], b2[2*h2], b2[2*h2+1]);
                        mma_s8(accC[mt][nt*2+h2], a2[mt], b1[2*h2], b1[2*h2+1]);
                    }
                }
            }
        }
        __syncthreads();
    }

    #pragma unroll
    for (int mt = 0; mt < 2; ++mt) {
        int r = rowBase + wm * 32 + mt * 16 + (lane >> 2);
        float sa0 = sA[r], sa1 = sA[r + 8];
        #pragma unroll
        for (int j8 = 0; j8 < 8; ++j8) {
            int cc = colBase + wn * 64 + j8 * 8 + 2 * (lane & 3);
            float sb0 = sB[cc], sb1 = sB[cc + 1];
            float v0 = sa0 * sb0 * ((float)accP[mt][j8][0] + (float)accC[mt][j8][0] * 0.0078125f);
            float v1 = sa0 * sb1 * ((float)accP[mt][j8][1] + (float)accC[mt][j8][1] * 0.0078125f);
            float v2 = sa1 * sb0 * ((float)accP[mt][j8][2] + (float)accC[mt][j8][2] * 0.0078125f);
            float v3 = sa1 * sb1 * ((float)accP[mt][j8][3] + (float)accC[mt][j8][3] * 0.0078125f);
            if (ADDC) {
                float2 x0 = *(const float2*)(ADD + (size_t)r * ldc + cc);
                float2 x1 = *(const float2*)(ADD + (size_t)(r + 8) * ldc + cc);
                v0 += x0.x; v1 += x0.y; v2 += x1.x; v3 += x1.y;
            }
            *(float2*)(C + (size_t)r * ldc + cc)       = make_float2(v0, v1);
            *(float2*)(C + (size_t)(r + 8) * ldc + cc) = make_float2(v2, v3);
        }
    }
}

// ---------------- host launcher ----------------
extern "C" void kernel_launch(void* const* d_in, const int* in_sizes, int n_in,
                              void* d_out, int out_size)
{
    const float* hs    = (const float*)d_in[0];
    const float* resid = (const float*)d_in[1];
    const float* cosp  = (const float*)d_in[2];
    const float* sinp  = (const float*)d_in[3];
    const float* w_qkv = (const float*)d_in[4];
    const float* w_o   = (const float*)d_in[5];
    const float* w_gu  = (const float*)d_in[6];
    const float* w_dn  = (const float*)d_in[7];
    const float* ln1   = (const float*)d_in[8];
    const float* ln2   = (const float*)d_in[9];

    float* out     = (float*)d_out;
    float* mlp_out = out;
    float* res2    = out + (size_t)Tc * Hc;

    float *p_res1, *p_qkv, *p_scores, *p_gu;
    cudaGetSymbolAddress((void**)&p_res1,   g_res1);
    cudaGetSymbolAddress((void**)&p_qkv,    g_qkv);
    cudaGetSymbolAddress((void**)&p_scores, g_scores);
    cudaGetSymbolAddress((void**)&p_gu,     g_gu);
    __nv_bfloat16 *qh,*ql,*kh,*kl,*vth,*vtl,*ph,*pl;
    cudaGetSymbolAddress((void**)&qh,  g_q_hi);  cudaGetSymbolAddress((void**)&ql,  g_q_lo);
    cudaGetSymbolAddress((void**)&kh,  g_k_hi);  cudaGetSymbolAddress((void**)&kl,  g_k_lo);
    cudaGetSymbolAddress((void**)&vth, g_vt_hi); cudaGetSymbolAddress((void**)&vtl, g_vt_lo);
    cudaGetSymbolAddress((void**)&ph,  g_p_hi);  cudaGetSymbolAddress((void**)&pl,  g_p_lo);
    signed char *nq1,*nq2,*atq1,*atq2,*acq1,*acq2;
    signed char *wq1,*wq2,*oq1,*oq2,*gq1,*gq2,*dq1,*dq2;
    float *ns,*ats,*acs,*wqs,*wos,*wgs,*wds;
    cudaGetSymbolAddress((void**)&nq1,  g_n_q1);   cudaGetSymbolAddress((void**)&nq2,  g_n_q2);
    cudaGetSymbolAddress((void**)&ns,   g_n_s);
    cudaGetSymbolAddress((void**)&atq1, g_at_q1);  cudaGetSymbolAddress((void**)&atq2, g_at_q2);
    cudaGetSymbolAddress((void**)&ats,  g_at_s);
    cudaGetSymbolAddress((void**)&acq1, g_ac_q1);  cudaGetSymbolAddress((void**)&acq2, g_ac_q2);
    cudaGetSymbolAddress((void**)&acs,  g_ac_s);
    cudaGetSymbolAddress((void**)&wq1,  g_wqkv_q1); cudaGetSymbolAddress((void**)&wq2, g_wqkv_q2);
    cudaGetSymbolAddress((void**)&wqs,  g_wqkv_s);
    cudaGetSymbolAddress((void**)&oq1,  g_wo_q1);   cudaGetSymbolAddress((void**)&oq2, g_wo_q2);
    cudaGetSymbolAddress((void**)&wos,  g_wo_s);
    cudaGetSymbolAddress((void**)&gq1,  g_wgu_q1);  cudaGetSymbolAddress((void**)&gq2, g_wgu_q2);
    cudaGetSymbolAddress((void**)&wgs,  g_wgu_s);
    cudaGetSymbolAddress((void**)&dq1,  g_wdn_q1);  cudaGetSymbolAddress((void**)&dq2, g_wdn_q2);
    cudaGetSymbolAddress((void**)&wds,  g_wdn_s);

    cudaFuncSetAttribute(hmma_gemm_kernel<true,false>,  cudaFuncAttributeMaxDynamicSharedMemorySize, gk::SMEM_SZ);
    cudaFuncSetAttribute(hmma_gemm_kernel<false,true>,  cudaFuncAttributeMaxDynamicSharedMemorySize, gk::SMEM_SZ);
    cudaFuncSetAttribute(s8_gemm_kernel<false>, cudaFuncAttributeMaxDynamicSharedMemorySize, qk8::SMEM_SZ);
    cudaFuncSetAttribute(s8_gemm_kernel<true>,  cudaFuncAttributeMaxDynamicSharedMemorySize, qk8::SMEM_SZ);

    // weight quantization
    colmax_kernel<<<3*Hc/256, 256>>>(w_qkv, Hc, 3*Hc, wqs);
    colmax_kernel<<<Hc/256,   256>>>(w_o,   Hc, Hc,   wos);
    colmax_kernel<<<2*Ic/256, 256>>>(w_gu,  Hc, 2*Ic, wgs);
    colmax_kernel<<<Hc/256,   256>>>(w_dn,  Ic, Hc,   wds);
    transpose_quant_kernel<<<dim3(3*Hc/32, Hc/32), 256>>>(w_qkv, 3*Hc, wq1, wq2, wqs, Hc);
    transpose_quant_kernel<<<dim3(Hc/32,   Hc/32), 256>>>(w_o,   Hc,   oq1, oq2, wos, Hc);
    transpose_quant_kernel<<<dim3(2*Ic/32, Hc/32), 256>>>(w_gu,  2*Ic, gq1, gq2, wgs, Hc);
    transpose_quant_kernel<<<dim3(Hc/32,   Ic/32), 256>>>(w_dn,  Hc,   dq1, dq2, wds, Ic);

    // 1) res1 + RMSNorm -> int8
    add_rmsnorm_q_kernel<<<Tc, 256>>>(hs, resid, ln1, p_res1, nq1, nq2, ns);

    // 2) qkv (s8)
    s8_gemm_kernel<false><<<dim3(3*Hc/128, Tc/128), 256, qk8::SMEM_SZ>>>(
        nq1, nq2, ns, wq1, wq2, wqs, p_qkv, nullptr, Hc, 3*Hc);

    // 3) rope + V transpose
    rope_kernel<<<(Tc*2*NHc*HALFc)/256, 256>>>(p_qkv, cosp, sinp, qh, ql, kh, kl);
    transpose_convert_kernel<<<dim3(HDc/32, Sc/32, Bc*NHc), 256>>>(
        p_qkv + 2*Hc, (long long)Sc*3*Hc, HDc, 3*Hc, vth, vtl, (long long)HDc*Sc, Sc);

    // 4) scores (bf16, causal)
    hmma_gemm_kernel<true,false><<<dim3(Sc/128, Sc/256, Bc*NHc), 256, gk::SMEM_SZ>>>(
        qh, ql, kh, kl, p_scores,
        HDc, Hc, Hc, Sc,
        (long long)Sc*Hc, HDc, (long long)Sc*Hc, HDc,
        (long long)NHc*Sc*Sc, (long long)Sc*Sc, SCALEc);

    // 5) softmax
    softmax_kernel<<<dim3(Sc, Bc*NHc), 256>>>(p_scores, ph, pl);

    // 6) PV (bf16, K-limited) -> fp32 attn [T,H] (reuses g_scores)
    hmma_gemm_kernel<false,true><<<dim3(1, Sc/256, Bc*NHc), 256, gk::SMEM_SZ>>>(
        ph, pl, vth, vtl, p_scores,
        Sc, Sc, Sc, Hc,
        (long long)NHc*Sc*Sc, (long long)Sc*Sc,
        (long long)NHc*HDc*Sc, (long long)HDc*Sc,
        (long long)Sc*Hc, HDc, 1.f);

    // 7) quantize attn, then o-proj + res1 -> res2 (output)
    row_quant_kernel<<<Tc, 256>>>(p_scores, Hc, atq1, atq2, ats);
    s8_gemm_kernel<true><<<dim3(Hc/128, Tc/128), 256, qk8::SMEM_SZ>>>(
        atq1, atq2, ats, oq1, oq2, wos, res2, p_res1, Hc, Hc);

    // 8) RMSNorm(res2) -> int8
    add_rmsnorm_q_kernel<<<Tc, 256>>>(res2, nullptr, ln2, nullptr, nq1, nq2, ns);

    // 9) gate/up (s8)
    s8_gemm_kernel<false><<<dim3(2*Ic/128, Tc/128), 256, qk8::SMEM_SZ>>>(
        nq1, nq2, ns, gq1, gq2, wgs, p_gu, nullptr, Hc, 2*Ic);

    // 10) silu -> fp32 (g_qkv scratch), quantize
    silu_fp32_kernel<<<dim3(Ic/256, Tc), 256>>>(p_gu, p_qkv);
    row_quant_kernel<<<Tc, 256>>>(p_qkv, Ic, acq1, acq2, acs);

    // 11) down (s8) -> mlp_out
    s8_gemm_kernel<false><<<dim3(Hc/128, Tc/128), 256, qk8::SMEM_SZ>>>(
        acq1, acq2, acs, dq1, dq2, wds, mlp_out, nullptr, Ic, Hc);
}

// round 9
// speedup vs baseline: 2.4159x; 2.4159x over previous
#include <cuda_runtime.h>
#include <cuda_bf16.h>
#include <math.h>
#include <stdint.h>

namespace {
constexpr int Bc  = 2;
constexpr int Sc  = 2048;
constexpr int Hc  = 4096;
constexpr int NHc = 32;
constexpr int HDc = 128;
constexpr int Ic  = 11008;
constexpr int Tc  = Bc * Sc;
constexpr int HALFc = HDc / 2;
constexpr float EPSc = 1e-6f;
constexpr float SCALEc = 0.08838834764831843f;
}

// ---------------- device scratch ----------------
__device__ float g_res1  [(size_t)Tc * Hc];
__device__ float g_qkv   [(size_t)Tc * 3 * Hc];
__device__ float g_scores[(size_t)Bc * NHc * Sc * Sc];
__device__ float g_gu    [(size_t)Tc * 2 * Ic];

__device__ __nv_bfloat16 g_n_hi [(size_t)Tc * Hc],  g_n_lo [(size_t)Tc * Hc];
__device__ __nv_bfloat16 g_q_hi [(size_t)Tc * Hc],  g_q_lo [(size_t)Tc * Hc];
__device__ __nv_bfloat16 g_k_hi [(size_t)Tc * Hc],  g_k_lo [(size_t)Tc * Hc];
__device__ __nv_bfloat16 g_vt_hi[(size_t)Tc * Hc],  g_vt_lo[(size_t)Tc * Hc];
__device__ __nv_bfloat16 g_p_hi [(size_t)Bc * NHc * Sc * Sc];
__device__ __nv_bfloat16 g_p_lo [(size_t)Bc * NHc * Sc * Sc];
__device__ __nv_bfloat16 g_at_hi[(size_t)Tc * Hc],  g_at_lo[(size_t)Tc * Hc];
__device__ __nv_bfloat16 g_ac_hi[(size_t)Tc * Ic],  g_ac_lo[(size_t)Tc * Ic];
__device__ __nv_bfloat16 g_wqkv_hi[(size_t)Hc * 3 * Hc], g_wqkv_lo[(size_t)Hc * 3 * Hc];
__device__ __nv_bfloat16 g_wo_hi  [(size_t)Hc * Hc],     g_wo_lo  [(size_t)Hc * Hc];
__device__ __nv_bfloat16 g_wgu_hi [(size_t)Hc * 2 * Ic], g_wgu_lo [(size_t)Hc * 2 * Ic];
__device__ __nv_bfloat16 g_wdn_hi [(size_t)Ic * Hc],     g_wdn_lo [(size_t)Ic * Hc];

// ---------------- helpers ----------------
__device__ __forceinline__ uint32_t smem_u32(const void* p) {
    return (uint32_t)__cvta_generic_to_shared(p);
}
__device__ __forceinline__ void ldsm_x4(uint32_t (&r)[4], uint32_t addr) {
    asm volatile("ldmatrix.sync.aligned.m8n8.x4.shared.b16 {%0,%1,%2,%3}, [%4];"
                 : "=r"(r[0]), "=r"(r[1]), "=r"(r[2]), "=r"(r[3]) : "r"(addr));
}
__device__ __forceinline__ void mma_bf16(float (&d)[4], const uint32_t (&a)[4],
                                         uint32_t b0, uint32_t b1) {
    asm volatile("mma.sync.aligned.m16n8k16.row.col.f32.bf16.bf16.f32 "
        "{%0,%1,%2,%3}, {%4,%5,%6,%7}, {%8,%9}, {%0,%1,%2,%3};"
        : "+f"(d[0]), "+f"(d[1]), "+f"(d[2]), "+f"(d[3])
        : "r"(a[0]), "r"(a[1]), "r"(a[2]), "r"(a[3]), "r"(b0), "r"(b1));
}
__device__ __forceinline__ void cp_async16(uint32_t dst, const void* src) {
    asm volatile("cp.async.cg.shared.global [%0], [%1], 16;" :: "r"(dst), "l"(src));
}
#define CP_COMMIT() asm volatile("cp.async.commit_group;" ::: "memory")
#define CP_WAIT(n)  asm volatile("cp.async.wait_group %0;" :: "n"(n) : "memory")
__device__ __forceinline__ void split2(float v, __nv_bfloat16& h, __nv_bfloat16& l) {
    h = __float2bfloat16(v);
    l = __float2bfloat16(v - __bfloat162float(h));
}

// ---------------- block reductions (256 thr) ----------------
__device__ __forceinline__ float block_reduce_sum_256(float v) {
    #pragma unroll
    for (int o = 16; o > 0; o >>= 1) v += __shfl_down_sync(0xffffffffu, v, o);
    __shared__ float red[8];
    int w = threadIdx.x >> 5, l = threadIdx.x & 31;
    if (l == 0) red[w] = v;
    __syncthreads();
    if (w == 0) {
        float x = (l < 8) ? red[l] : 0.f;
        #pragma unroll
        for (int o = 4; o > 0; o >>= 1) x += __shfl_down_sync(0xffu, x, o);
        if (l == 0) red[0] = x;
    }
    __syncthreads();
    float r = red[0];
    __syncthreads();
    return r;
}
__device__ __forceinline__ float block_reduce_max_256(float v) {
    #pragma unroll
    for (int o = 16; o > 0; o >>= 1) v = fmaxf(v, __shfl_down_sync(0xffffffffu, v, o));
    __shared__ float red[8];
    int w = threadIdx.x >> 5, l = threadIdx.x & 31;
    if (l == 0) red[w] = v;
    __syncthreads();
    if (w == 0) {
        float x = (l < 8) ? red[l] : -INFINITY;
        #pragma unroll
        for (int o = 4; o > 0; o >>= 1) x = fmaxf(x, __shfl_down_sync(0xffu, x, o));
        if (l == 0) red[0] = x;
    }
    __syncthreads();
    float r = red[0];
    __syncthreads();
    return r;
}

// ---------------- add + RMSNorm -> hi/lo ----------------
__global__ __launch_bounds__(256) void add_rmsnorm_kernel(
    const float* __restrict__ a, const float* __restrict__ b,
    const float* __restrict__ w, float* __restrict__ sum_out,
    __nv_bfloat16* __restrict__ ohi, __nv_bfloat16* __restrict__ olo)
{
    int row = blockIdx.x;
    const float4* a4 = (const float4*)(a + (size_t)row * Hc);
    const float4* b4 = b ? (const float4*)(b + (size_t)row * Hc) : nullptr;
    const float4* w4 = (const float4*)w;
    float4* s4 = sum_out ? (float4*)(sum_out + (size_t)row * Hc) : nullptr;
    __nv_bfloat162* oh2 = (__nv_bfloat162*)(ohi + (size_t)row * Hc);
    __nv_bfloat162* ol2 = (__nv_bfloat162*)(olo + (size_t)row * Hc);

    float4 v[4];
    float ss = 0.f;
    #pragma unroll
    for (int it = 0; it < 4; it++) {
        int idx = threadIdx.x + it * 256;
        float4 va = a4[idx];
        if (b4) { float4 vb = b4[idx]; va.x += vb.x; va.y += vb.y; va.z += vb.z; va.w += vb.w; }
        v[it] = va;
        ss += va.x * va.x + va.y * va.y + va.z * va.z + va.w * va.w;
    }
    float tot = block_reduce_sum_256(ss);
    float scale = rsqrtf(tot / (float)Hc + EPSc);
    #pragma unroll
    for (int it = 0; it < 4; it++) {
        int idx = threadIdx.x + it * 256;
        if (s4) s4[idx] = v[it];
        float4 vw = w4[idx];
        float y0 = v[it].x * scale * vw.x, y1 = v[it].y * scale * vw.y;
        float y2 = v[it].z * scale * vw.z, y3 = v[it].w * scale * vw.w;
        __nv_bfloat16 h0,l0,h1,l1,h2,l2,h3,l3;
        split2(y0,h0,l0); split2(y1,h1,l1); split2(y2,h2,l2); split2(y3,h3,l3);
        oh2[idx*2]   = __nv_bfloat162(h0,h1);
        oh2[idx*2+1] = __nv_bfloat162(h2,h3);
        ol2[idx*2]   = __nv_bfloat162(l0,l1);
        ol2[idx*2+1] = __nv_bfloat162(l2,l3);
    }
}

// ---------------- RoPE: fp32 qkv -> Q/K hi/lo ----------------
__global__ __launch_bounds__(256) void rope_kernel(
    const float* __restrict__ qkv, const float* __restrict__ cosp,
    const float* __restrict__ sinp,
    __nv_bfloat16* __restrict__ qhi, __nv_bfloat16* __restrict__ qlo,
    __nv_bfloat16* __restrict__ khi, __nv_bfloat16* __restrict__ klo)
{
    int idx = blockIdx.x * 256 + threadIdx.x;
    int d = idx & (HALFc - 1);
    int h = (idx >> 6) & (NHc - 1);
    int m = (idx >> 11) & 1;
    int t = idx >> 12;
    const float* p = qkv + (size_t)t * (3 * Hc) + m * Hc + h * HDc + d;
    float x1 = p[0], x2 = p[HALFc];
    float c = cosp[(size_t)t * HALFc + d];
    float s = sinp[(size_t)t * HALFc + d];
    float y1 = x1 * c - x2 * s;
    float y2 = x1 * s + x2 * c;
    __nv_bfloat16* dh = (m ? khi : qhi) + (size_t)t * Hc + h * HDc + d;
    __nv_bfloat16* dl = (m ? klo : qlo) + (size_t)t * Hc + h * HDc + d;
    __nv_bfloat16 h1, l1, h2, l2;
    split2(y1, h1, l1); split2(y2, h2, l2);
    dh[0] = h1; dh[HALFc] = h2;
    dl[0] = l1; dl[HALFc] = l2;
}

// ------- transpose fp32 [Y,X] (ld=in_ld) -> hi/lo [X,Y]; batched via z -------
__global__ __launch_bounds__(256) void transpose_convert_kernel(
    const float* __restrict__ in, long long inSb, long long inSh, int in_ld,
    __nv_bfloat16* __restrict__ ohi, __nv_bfloat16* __restrict__ olo,
    long long outSz, int Y)
{
    __shared__ float tile[32][33];
    int z = blockIdx.z, zb = z / NHc, zh = z % NHc;
    const float* inp = in + zb * inSb + zh * inSh;
    __nv_bfloat16* oh = ohi + (long long)z * outSz;
    __nv_bfloat16* ol = olo + (long long)z * outSz;
    int tx = threadIdx.x & 31, ty = threadIdx.x >> 5;
    int gx = blockIdx.x * 32 + tx;
    #pragma unroll
    for (int i = 0; i < 4; i++) {
        int gy = blockIdx.y * 32 + ty + i * 8;
        tile[ty + i * 8][tx] = inp[(size_t)gy * in_ld + gx];
    }
    __syncthreads();
    int ox = blockIdx.y * 32 + tx;
    #pragma unroll
    for (int i = 0; i < 4; i++) {
        int oy = blockIdx.x * 32 + ty + i * 8;
        __nv_bfloat16 h, l;
        split2(tile[tx][ty + i * 8], h, l);
        oh[(size_t)oy * Y + ox] = h;
        ol[(size_t)oy * Y + ox] = l;
    }
}

// ------- causal softmax -> P hi/lo (zero-fill to 256-aligned edge) -------
__global__ __launch_bounds__(256) void softmax_kernel(
    const float* __restrict__ scores,
    __nv_bfloat16* __restrict__ phi, __nv_bfloat16* __restrict__ plo)
{
    int i = blockIdx.x;
    int z = blockIdx.y;
    const float* row = scores + (size_t)z * Sc * Sc + (size_t)i * Sc;
    __nv_bfloat16* ph = phi + (size_t)z * Sc * Sc + (size_t)i * Sc;
    __nv_bfloat16* pl = plo + (size_t)z * Sc * Sc + (size_t)i * Sc;
    int nvalid = i + 1;

    float vals[8];
    float mx = -INFINITY;
    #pragma unroll
    for (int it = 0; it < 8; it++) {
        int j = threadIdx.x + it * 256;
        float v = (j < nvalid) ? row[j] : -INFINITY;
        vals[it] = v;
        mx = fmaxf(mx, v);
    }
    float M = block_reduce_max_256(mx);
    float sum = 0.f;
    #pragma unroll
    for (int it = 0; it < 8; it++) {
        int j = threadIdx.x + it * 256;
        float e = (j < nvalid) ? __expf(vals[it] - M) : 0.f;
        vals[it] = e;
        sum += e;
    }
    float tot = block_reduce_sum_256(sum);
    float inv = 1.f / tot;
    int zero_end = ((i >> 8) + 1) << 8;
    #pragma unroll
    for (int it = 0; it < 8; it++) {
        int j = threadIdx.x + it * 256;
        if (j < zero_end) {
            __nv_bfloat16 h, l;
            split2(vals[it] * inv, h, l);
            ph[j] = h; pl[j] = l;
        }
    }
}

// ---------------- SiLU(gate)*up -> hi/lo ----------------
__global__ __launch_bounds__(256) void silu_mul_kernel(
    const float* __restrict__ gu,
    __nv_bfloat16* __restrict__ ahi, __nv_bfloat16* __restrict__ alo)
{
    int t = blockIdx.y;
    int i = blockIdx.x * 256 + threadIdx.x;
    float g = gu[(size_t)t * (2 * Ic) + i];
    float u = gu[(size_t)t * (2 * Ic) + Ic + i];
    float s = g / (1.f + __expf(-g));
    __nv_bfloat16 h, l;
    split2(s * u, h, l);
    ahi[(size_t)t * Ic + i] = h;
    alo[(size_t)t * Ic + i] = l;
}

// ------------------------------------------------------------------
// HMMA GEMM: C = alpha*(A@B^T)[+ADD]. A:[M,K], B:[N,K] hi/lo K-major
// bf16 planes. BM=256, BN=128, BK=32. 512 threads / 16 warps,
// warp tile 32x64 (8m x 2n warp grid), 3-stage cp.async pipeline.
// 3 passes (hh, hl, lh) into shared fp32 accumulators.
// ------------------------------------------------------------------
namespace gk {
constexpr int BM = 256, BN = 128, BK = 32, SROW = 40;
constexpr int AOFF_L = BM * SROW * 2;           // 20480
constexpr int BOFF_H = 2 * AOFF_L;              // 40960
constexpr int BOFF_L = BOFF_H + BN * SROW * 2;  // 51200
constexpr int STAGE  = BOFF_L + BN * SROW * 2;  // 61440
constexpr int NSTG   = 3;
constexpr int SMEM_SZ = NSTG * STAGE;           // 184320
}

template<bool CAUSAL, bool KLIM, bool ADDC, bool HILO>
__global__ __launch_bounds__(512, 1) void hmma_gemm_kernel(
    const __nv_bfloat16* __restrict__ Ahi, const __nv_bfloat16* __restrict__ Alo,
    const __nv_bfloat16* __restrict__ Bhi, const __nv_bfloat16* __restrict__ Blo,
    float* __restrict__ Cf, __nv_bfloat16* __restrict__ Chi, __nv_bfloat16* __restrict__ Clo,
    const float* __restrict__ ADDp,
    int K, int lda, int ldb, int ldc,
    long long sAb, long long sAh_, long long sBb, long long sBh_,
    long long sCb, long long sCh_, float alpha)
{
    using namespace gk;
    int rowBase = blockIdx.y * BM;
    int colBase = blockIdx.x * BN;
    if (CAUSAL && colBase > rowBase + BM - 1) return;

    extern __shared__ char smraw[];
    uint32_t sbase = smem_u32(smraw);

    int tid = threadIdx.x;
    int wid = tid >> 5, lane = tid & 31;
    int wm = wid & 7, wn = wid >> 3;          // 8 x 2 warp grid, 32x64 tiles

    int z = blockIdx.z, zb = z / NHc, zh = z % NHc;
    const __nv_bfloat16* Ah = Ahi + zb * sAb + zh * sAh_;
    const __nv_bfloat16* Al = Alo + zb * sAb + zh * sAh_;
    const __nv_bfloat16* Bh = Bhi + zb * sBb + zh * sBh_;
    const __nv_bfloat16* Bl = Blo + zb * sBb + zh * sBh_;

    int kEnd = KLIM ? min(K, rowBase + BM) : K;
    int nch  = kEnd / BK;

    float acc[2][8][4];
    #pragma unroll
    for (int a = 0; a < 2; a++)
        #pragma unroll
        for (int b = 0; b < 8; b++)
            #pragma unroll
            for (int c = 0; c < 4; c++) acc[a][b][c] = 0.f;

    // cp.async mapping (512 thr): row = tid>>2 (0..127), seg = (tid&3)*8 elems
    int ar = tid >> 2, sg = (tid & 3) * 8;
    uint32_t soff = (uint32_t)(ar * SROW + sg) * 2;

    auto issue = [&](int c) {
        int k0 = c * BK;
        uint32_t st = sbase + (c % NSTG) * STAGE;
        #pragma unroll
        for (int it = 0; it < 2; it++) {            // A: 256 rows
            int r = ar + it * 128;
            uint32_t o = soff + (uint32_t)(it * 128 * SROW) * 2;
            cp_async16(st + o,          Ah + (size_t)(rowBase + r) * lda + k0 + sg);
            cp_async16(st + AOFF_L + o, Al + (size_t)(rowBase + r) * lda + k0 + sg);
        }
        {                                            // B: 128 rows
            cp_async16(st + BOFF_H + soff, Bh + (size_t)(colBase + ar) * ldb + k0 + sg);
            cp_async16(st + BOFF_L + soff, Bl + (size_t)(colBase + ar) * ldb + k0 + sg);
        }
    };

    // ldmatrix lane addressing
    int mat = lane >> 3, r8 = lane & 7;
    int a_row = (mat & 1) * 8 + r8, a_k = (mat >> 1) * 8;
    int b_n   = (mat >> 1) * 8 + r8, b_k = (mat & 1) * 8;

    issue(0); CP_COMMIT();
    if (nch > 1) { issue(1); CP_COMMIT(); }
    else CP_COMMIT();

    for (int c = 0; c < nch; ++c) {
        if (c + 2 < nch) issue(c + 2);
        CP_COMMIT();
        CP_WAIT(2);
        __syncthreads();

        uint32_t st = sbase + (c % NSTG) * STAGE;
        #pragma unroll
        for (int ks = 0; ks < 2; ++ks) {
            uint32_t ah[2][4], al[2][4];
            #pragma unroll
            for (int mt = 0; mt < 2; ++mt) {
                uint32_t off = (uint32_t)((wm * 32 + mt * 16 + a_row) * SROW
                                          + ks * 16 + a_k) * 2;
                ldsm_x4(ah[mt], st + off);
                ldsm_x4(al[mt], st + AOFF_L + off);
            }
            #pragma unroll
            for (int nt = 0; nt < 4; ++nt) {
                uint32_t boff = (uint32_t)((wn * 64 + nt * 16 + b_n) * SROW
                                           + ks * 16 + b_k) * 2;
                uint32_t bh[4], bl[4];
                ldsm_x4(bh, st + BOFF_H + boff);
                ldsm_x4(bl, st + BOFF_L + boff);
                #pragma unroll
                for (int mt = 0; mt < 2; ++mt) {
                    #pragma unroll
                    for (int h2 = 0; h2 < 2; ++h2) {
                        mma_bf16(acc[mt][nt*2+h2], ah[mt], bh[2*h2], bh[2*h2+1]);
                        mma_bf16(acc[mt][nt*2+h2], ah[mt], bl[2*h2], bl[2*h2+1]);
                        mma_bf16(acc[mt][nt*2+h2], al[mt], bh[2*h2], bh[2*h2+1]);
                    }
                }
            }
        }
        __syncthreads();
    }

    // ---------------- epilogue (warp tile 32x64) ----------------
    float*         Cfz = Cf  ? Cf  + zb * sCb + zh * sCh_ : nullptr;
    __nv_bfloat16* Chz = Chi ? Chi + zb * sCb + zh * sCh_ : nullptr;
    __nv_bfloat16* Clz = Clo ? Clo + zb * sCb + zh * sCh_ : nullptr;
    const float*   ADz = ADDp ? ADDp + zb * sCb + zh * sCh_ : nullptr;

    #pragma unroll
    for (int mt = 0; mt < 2; ++mt) {
        int r = rowBase + wm * 32 + mt * 16 + (lane >> 2);
        #pragma unroll
        for (int j8 = 0; j8 < 8; ++j8) {
            int cc = colBase + wn * 64 + j8 * 8 + 2 * (lane & 3);
            float v0 = acc[mt][j8][0] * alpha;
            float v1 = acc[mt][j8][1] * alpha;
            float v2 = acc[mt][j8][2] * alpha;
            float v3 = acc[mt][j8][3] * alpha;
            if (ADDC) {
                float2 a0 = *(const float2*)(ADz + (size_t)r * ldc + cc);
                float2 a1 = *(const float2*)(ADz + (size_t)(r + 8) * ldc + cc);
                v0 += a0.x; v1 += a0.y; v2 += a1.x; v3 += a1.y;
            }
            if (!HILO) {
                *(float2*)(Cfz + (size_t)r * ldc + cc)       = make_float2(v0, v1);
                *(float2*)(Cfz + (size_t)(r + 8) * ldc + cc) = make_float2(v2, v3);
            } else {
                __nv_bfloat16 h0,l0,h1,l1,h2,l2,h3,l3;
                split2(v0,h0,l0); split2(v1,h1,l1);
                split2(v2,h2,l2); split2(v3,h3,l3);
                *(__nv_bfloat162*)(Chz + (size_t)r * ldc + cc)       = __nv_bfloat162(h0,h1);
                *(__nv_bfloat162*)(Clz + (size_t)r * ldc + cc)       = __nv_bfloat162(l0,l1);
                *(__nv_bfloat162*)(Chz + (size_t)(r + 8) * ldc + cc) = __nv_bfloat162(h2,h3);
                *(__nv_bfloat162*)(Clz + (size_t)(r + 8) * ldc + cc) = __nv_bfloat162(l2,l3);
            }
        }
    }
}

// ---------------- host launcher ----------------
extern "C" void kernel_launch(void* const* d_in, const int* in_sizes, int n_in,
                              void* d_out, int out_size)
{
    const float* hs    = (const float*)d_in[0];
    const float* resid = (const float*)d_in[1];
    const float* cosp  = (const float*)d_in[2];
    const float* sinp  = (const float*)d_in[3];
    const float* w_qkv = (const float*)d_in[4];
    const float* w_o   = (const float*)d_in[5];
    const float* w_gu  = (const float*)d_in[6];
    const float* w_dn  = (const float*)d_in[7];
    const float* ln1   = (const float*)d_in[8];
    const float* ln2   = (const float*)d_in[9];

    float* out     = (float*)d_out;
    float* mlp_out = out;
    float* res2    = out + (size_t)Tc * Hc;

    float *p_res1, *p_qkv, *p_scores, *p_gu;
    cudaGetSymbolAddress((void**)&p_res1,   g_res1);
    cudaGetSymbolAddress((void**)&p_qkv,    g_qkv);
    cudaGetSymbolAddress((void**)&p_scores, g_scores);
    cudaGetSymbolAddress((void**)&p_gu,     g_gu);
    __nv_bfloat16 *nh,*nl,*qh,*ql,*kh,*kl,*vth,*vtl,*ph,*pl,*ath,*atl,*ach,*acl;
    __nv_bfloat16 *wqh,*wql,*woh,*wol,*wgh,*wgl,*wdh,*wdl;
    cudaGetSymbolAddress((void**)&nh,  g_n_hi);  cudaGetSymbolAddress((void**)&nl,  g_n_lo);
    cudaGetSymbolAddress((void**)&qh,  g_q_hi);  cudaGetSymbolAddress((void**)&ql,  g_q_lo);
    cudaGetSymbolAddress((void**)&kh,  g_k_hi);  cudaGetSymbolAddress((void**)&kl,  g_k_lo);
    cudaGetSymbolAddress((void**)&vth, g_vt_hi); cudaGetSymbolAddress((void**)&vtl, g_vt_lo);
    cudaGetSymbolAddress((void**)&ph,  g_p_hi);  cudaGetSymbolAddress((void**)&pl,  g_p_lo);
    cudaGetSymbolAddress((void**)&ath, g_at_hi); cudaGetSymbolAddress((void**)&atl, g_at_lo);
    cudaGetSymbolAddress((void**)&ach, g_ac_hi); cudaGetSymbolAddress((void**)&acl, g_ac_lo);
    cudaGetSymbolAddress((void**)&wqh, g_wqkv_hi); cudaGetSymbolAddress((void**)&wql, g_wqkv_lo);
    cudaGetSymbolAddress((void**)&woh, g_wo_hi);   cudaGetSymbolAddress((void**)&wol, g_wo_lo);
    cudaGetSymbolAddress((void**)&wgh, g_wgu_hi);  cudaGetSymbolAddress((void**)&wgl, g_wgu_lo);
    cudaGetSymbolAddress((void**)&wdh, g_wdn_hi);  cudaGetSymbolAddress((void**)&wdl, g_wdn_lo);

    cudaFuncSetAttribute(hmma_gemm_kernel<false,false,false,false>, cudaFuncAttributeMaxDynamicSharedMemorySize, gk::SMEM_SZ);
    cudaFuncSetAttribute(hmma_gemm_kernel<true, false,false,false>, cudaFuncAttributeMaxDynamicSharedMemorySize, gk::SMEM_SZ);
    cudaFuncSetAttribute(hmma_gemm_kernel<false,true, false,true >, cudaFuncAttributeMaxDynamicSharedMemorySize, gk::SMEM_SZ);
    cudaFuncSetAttribute(hmma_gemm_kernel<false,false,true, false>, cudaFuncAttributeMaxDynamicSharedMemorySize, gk::SMEM_SZ);

    // weight transposes + hi/lo conversion
    transpose_convert_kernel<<<dim3(3*Hc/32, Hc/32, 1), 256>>>(w_qkv, 0, 0, 3*Hc, wqh, wql, 0, Hc);
    transpose_convert_kernel<<<dim3(Hc/32,   Hc/32, 1), 256>>>(w_o,   0, 0, Hc,   woh, wol, 0, Hc);
    transpose_convert_kernel<<<dim3(2*Ic/32, Hc/32, 1), 256>>>(w_gu,  0, 0, 2*Ic, wgh, wgl, 0, Hc);
    transpose_convert_kernel<<<dim3(Hc/32,   Ic/32, 1), 256>>>(w_dn,  0, 0, Hc,   wdh, wdl, 0, Ic);

    // 1) res1 + RMSNorm -> n planes
    add_rmsnorm_kernel<<<Tc, 256>>>(hs, resid, ln1, p_res1, nh, nl);

    // 2) qkv = normed @ w_qkv (fp32)
    hmma_gemm_kernel<false,false,false,false><<<dim3(3*Hc/128, Tc/256, 1), 512, gk::SMEM_SZ>>>(
        nh, nl, wqh, wql, p_qkv, nullptr, nullptr, nullptr,
        Hc, Hc, Hc, 3*Hc, 0,0,0,0,0,0, 1.f);

    // 3) RoPE -> q/k planes ; V transpose -> vt planes
    rope_kernel<<<(Tc*2*NHc*HALFc)/256, 256>>>(p_qkv, cosp, sinp, qh, ql, kh, kl);
    transpose_convert_kernel<<<dim3(HDc/32, Sc/32, Bc*NHc), 256>>>(
        p_qkv + 2*Hc, (long long)Sc*3*Hc, HDc, 3*Hc, vth, vtl, (long long)HDc*Sc, Sc);

    // 4) scores = scale * Q @ K^T (causal skip)
    hmma_gemm_kernel<true,false,false,false><<<dim3(Sc/128, Sc/256, Bc*NHc), 512, gk::SMEM_SZ>>>(
        qh, ql, kh, kl, p_scores, nullptr, nullptr, nullptr,
        HDc, Hc, Hc, Sc,
        (long long)Sc*Hc, HDc, (long long)Sc*Hc, HDc,
        (long long)NHc*Sc*Sc, (long long)Sc*Sc, SCALEc);

    // 5) softmax -> P planes
    softmax_kernel<<<dim3(Sc, Bc*NHc), 256>>>(p_scores, ph, pl);

    // 6) attn = P @ V (K-limited to rowBase+256) -> at planes (hi/lo)
    hmma_gemm_kernel<false,true,false,true><<<dim3(1, Sc/256, Bc*NHc), 512, gk::SMEM_SZ>>>(
        ph, pl, vth, vtl, nullptr, ath, atl, nullptr,
        Sc, Sc, Sc, Hc,
        (long long)NHc*Sc*Sc, (long long)Sc*Sc,
        (long long)NHc*HDc*Sc, (long long)HDc*Sc,
        (long long)Sc*Hc, HDc, 1.f);

    // 7) res2 = attn @ w_o + res1 (fp32, into output)
    hmma_gemm_kernel<false,false,true,false><<<dim3(Hc/128, Tc/256, 1), 512, gk::SMEM_SZ>>>(
        ath, atl, woh, wol, res2, nullptr, nullptr, p_res1,
        Hc, Hc, Hc, Hc, 0,0,0,0,0,0, 1.f);

    // 8) RMSNorm(res2) -> n planes
    add_rmsnorm_kernel<<<Tc, 256>>>(res2, nullptr, ln2, nullptr, nh, nl);

    // 9) gu = normed2 @ w_gate_up (fp32)
    hmma_gemm_kernel<false,false,false,false><<<dim3(2*Ic/128, Tc/256, 1), 512, gk::SMEM_SZ>>>(
        nh, nl, wgh, wgl, p_gu, nullptr, nullptr, nullptr,
        Hc, Hc, Hc, 2*Ic, 0,0,0,0,0,0, 1.f);

    // 10) silu*up -> ac planes
    silu_mul_kernel<<<dim3(Ic/256, Tc), 256>>>(p_gu, ach, acl);

    // 11) mlp_out = act @ w_down (fp32, into output)
    hmma_gemm_kernel<false,false,false,false><<<dim3(Hc/128, Tc/256, 1), 512, gk::SMEM_SZ>>>(
        ach, acl, wdh, wdl, mlp_out, nullptr, nullptr, nullptr,
        Ic, Ic, Ic, Hc, 0,0,0,0,0,0, 1.f);
}

// round 12
// speedup vs baseline: 4.5022x; 1.8636x over previous
#include <cuda_runtime.h>
#include <cuda_bf16.h>
#include <cuda_fp16.h>
#include <math.h>
#include <stdint.h>

namespace {
constexpr int Bc  = 2;
constexpr int Sc  = 2048;
constexpr int Hc  = 4096;
constexpr int NHc = 32;
constexpr int HDc = 128;
constexpr int Ic  = 11008;
constexpr int Tc  = Bc * Sc;
constexpr int HALFc = HDc / 2;
constexpr float EPSc = 1e-6f;
constexpr float SCALEc = 0.08838834764831843f;
}

// ---------------- device scratch ----------------
__device__ float g_res1  [(size_t)Tc * Hc];
__device__ float g_qkv   [(size_t)Tc * 3 * Hc];
__device__ float g_scores[(size_t)Bc * NHc * Sc * Sc];
__device__ float g_gu    [(size_t)Tc * 2 * Ic];

__device__ __nv_bfloat16 g_n_hi [(size_t)Tc * Hc],  g_n_lo [(size_t)Tc * Hc];
__device__ __nv_bfloat16 g_q_hi [(size_t)Tc * Hc],  g_q_lo [(size_t)Tc * Hc];
__device__ __nv_bfloat16 g_k_hi [(size_t)Tc * Hc],  g_k_lo [(size_t)Tc * Hc];
__device__ __nv_bfloat16 g_vt_hi[(size_t)Tc * Hc],  g_vt_lo[(size_t)Tc * Hc];
__device__ __nv_bfloat16 g_p_hi [(size_t)Bc * NHc * Sc * Sc];
__device__ __nv_bfloat16 g_p_lo [(size_t)Bc * NHc * Sc * Sc];
__device__ __nv_bfloat16 g_wqkv_hi[(size_t)Hc * 3 * Hc], g_wqkv_lo[(size_t)Hc * 3 * Hc];

// fp16 single-plane tensors (post-attention path)
__device__ __half g_at_h [(size_t)Tc * Hc];
__device__ __half g_n2_h [(size_t)Tc * Hc];
__device__ __half g_ac_h [(size_t)Tc * Ic];
__device__ __half g_wo_h [(size_t)Hc * Hc];
__device__ __half g_wgu_h[(size_t)2 * Ic * Hc];
__device__ __half g_wdn_h[(size_t)Hc * Ic];

// ---------------- helpers ----------------
__device__ __forceinline__ uint32_t smem_u32(const void* p) {
    return (uint32_t)__cvta_generic_to_shared(p);
}
__device__ __forceinline__ void ldsm_x4(uint32_t (&r)[4], uint32_t addr) {
    asm volatile("ldmatrix.sync.aligned.m8n8.x4.shared.b16 {%0,%1,%2,%3}, [%4];"
                 : "=r"(r[0]), "=r"(r[1]), "=r"(r[2]), "=r"(r[3]) : "r"(addr));
}
__device__ __forceinline__ void mma_bf16(float (&d)[4], const uint32_t (&a)[4],
                                         uint32_t b0, uint32_t b1) {
    asm volatile("mma.sync.aligned.m16n8k16.row.col.f32.bf16.bf16.f32 "
        "{%0,%1,%2,%3}, {%4,%5,%6,%7}, {%8,%9}, {%0,%1,%2,%3};"
        : "+f"(d[0]), "+f"(d[1]), "+f"(d[2]), "+f"(d[3])
        : "r"(a[0]), "r"(a[1]), "r"(a[2]), "r"(a[3]), "r"(b0), "r"(b1));
}
__device__ __forceinline__ void mma_f16(float (&d)[4], const uint32_t (&a)[4],
                                        uint32_t b0, uint32_t b1) {
    asm volatile("mma.sync.aligned.m16n8k16.row.col.f32.f16.f16.f32 "
        "{%0,%1,%2,%3}, {%4,%5,%6,%7}, {%8,%9}, {%0,%1,%2,%3};"
        : "+f"(d[0]), "+f"(d[1]), "+f"(d[2]), "+f"(d[3])
        : "r"(a[0]), "r"(a[1]), "r"(a[2]), "r"(a[3]), "r"(b0), "r"(b1));
}
__device__ __forceinline__ void cp_async16(uint32_t dst, const void* src) {
    asm volatile("cp.async.cg.shared.global [%0], [%1], 16;" :: "r"(dst), "l"(src));
}
#define CP_COMMIT() asm volatile("cp.async.commit_group;" ::: "memory")
#define CP_WAIT(n)  asm volatile("cp.async.wait_group %0;" :: "n"(n) : "memory")
__device__ __forceinline__ void split2(float v, __nv_bfloat16& h, __nv_bfloat16& l) {
    h = __float2bfloat16(v);
    l = __float2bfloat16(v - __bfloat162float(h));
}

// ---------------- block reductions (256 thr) ----------------
__device__ __forceinline__ float block_reduce_sum_256(float v) {
    #pragma unroll
    for (int o = 16; o > 0; o >>= 1) v += __shfl_down_sync(0xffffffffu, v, o);
    __shared__ float red[8];
    int w = threadIdx.x >> 5, l = threadIdx.x & 31;
    if (l == 0) red[w] = v;
    __syncthreads();
    if (w == 0) {
        float x = (l < 8) ? red[l] : 0.f;
        #pragma unroll
        for (int o = 4; o > 0; o >>= 1) x += __shfl_down_sync(0xffu, x, o);
        if (l == 0) red[0] = x;
    }
    __syncthreads();
    float r = red[0];
    __syncthreads();
    return r;
}
__device__ __forceinline__ float block_reduce_max_256(float v) {
    #pragma unroll
    for (int o = 16; o > 0; o >>= 1) v = fmaxf(v, __shfl_down_sync(0xffffffffu, v, o));
    __shared__ float red[8];
    int w = threadIdx.x >> 5, l = threadIdx.x & 31;
    if (l == 0) red[w] = v;
    __syncthreads();
    if (w == 0) {
        float x = (l < 8) ? red[l] : -INFINITY;
        #pragma unroll
        for (int o = 4; o > 0; o >>= 1) x = fmaxf(x, __shfl_down_sync(0xffu, x, o));
        if (l == 0) red[0] = x;
    }
    __syncthreads();
    float r = red[0];
    __syncthreads();
    return r;
}

// ------- add + RMSNorm -> bf16 hi/lo OR fp16 single plane -------
__global__ __launch_bounds__(256) void add_rmsnorm_kernel(
    const float* __restrict__ a, const float* __restrict__ b,
    const float* __restrict__ w, float* __restrict__ sum_out,
    __nv_bfloat16* __restrict__ ohi, __nv_bfloat16* __restrict__ olo,
    __half* __restrict__ oh16)
{
    int row = blockIdx.x;
    const float4* a4 = (const float4*)(a + (size_t)row * Hc);
    const float4* b4 = b ? (const float4*)(b + (size_t)row * Hc) : nullptr;
    const float4* w4 = (const float4*)w;
    float4* s4 = sum_out ? (float4*)(sum_out + (size_t)row * Hc) : nullptr;

    float4 v[4];
    float ss = 0.f;
    #pragma unroll
    for (int it = 0; it < 4; it++) {
        int idx = threadIdx.x + it * 256;
        float4 va = a4[idx];
        if (b4) { float4 vb = b4[idx]; va.x += vb.x; va.y += vb.y; va.z += vb.z; va.w += vb.w; }
        v[it] = va;
        ss += va.x * va.x + va.y * va.y + va.z * va.z + va.w * va.w;
    }
    float tot = block_reduce_sum_256(ss);
    float scale = rsqrtf(tot / (float)Hc + EPSc);
    #pragma unroll
    for (int it = 0; it < 4; it++) {
        int idx = threadIdx.x + it * 256;
        if (s4) s4[idx] = v[it];
        float4 vw = w4[idx];
        float y0 = v[it].x * scale * vw.x, y1 = v[it].y * scale * vw.y;
        float y2 = v[it].z * scale * vw.z, y3 = v[it].w * scale * vw.w;
        if (oh16) {
            __half2* o2 = (__half2*)(oh16 + (size_t)row * Hc);
            o2[idx*2]   = __half2(__float2half_rn(y0), __float2half_rn(y1));
            o2[idx*2+1] = __half2(__float2half_rn(y2), __float2half_rn(y3));
        } else {
            __nv_bfloat162* oh2 = (__nv_bfloat162*)(ohi + (size_t)row * Hc);
            __nv_bfloat162* ol2 = (__nv_bfloat162*)(olo + (size_t)row * Hc);
            __nv_bfloat16 h0,l0,h1,l1,h2,l2,h3,l3;
            split2(y0,h0,l0); split2(y1,h1,l1); split2(y2,h2,l2); split2(y3,h3,l3);
            oh2[idx*2]   = __nv_bfloat162(h0,h1);
            oh2[idx*2+1] = __nv_bfloat162(h2,h3);
            ol2[idx*2]   = __nv_bfloat162(l0,l1);
            ol2[idx*2+1] = __nv_bfloat162(l2,l3);
        }
    }
}

// ---------------- RoPE: fp32 qkv -> Q/K bf16 hi/lo ----------------
__global__ __launch_bounds__(256) void rope_kernel(
    const float* __restrict__ qkv, const float* __restrict__ cosp,
    const float* __restrict__ sinp,
    __nv_bfloat16* __restrict__ qhi, __nv_bfloat16* __restrict__ qlo,
    __nv_bfloat16* __restrict__ khi, __nv_bfloat16* __restrict__ klo)
{
    int idx = blockIdx.x * 256 + threadIdx.x;
    int d = idx & (HALFc - 1);
    int h = (idx >> 6) & (NHc - 1);
    int m = (idx >> 11) & 1;
    int t = idx >> 12;
    const float* p = qkv + (size_t)t * (3 * Hc) + m * Hc + h * HDc + d;
    float x1 = p[0], x2 = p[HALFc];
    float c = cosp[(size_t)t * HALFc + d];
    float s = sinp[(size_t)t * HALFc + d];
    float y1 = x1 * c - x2 * s;
    float y2 = x1 * s + x2 * c;
    __nv_bfloat16* dh = (m ? khi : qhi) + (size_t)t * Hc + h * HDc + d;
    __nv_bfloat16* dl = (m ? klo : qlo) + (size_t)t * Hc + h * HDc + d;
    __nv_bfloat16 h1, l1, h2, l2;
    split2(y1, h1, l1); split2(y2, h2, l2);
    dh[0] = h1; dh[HALFc] = h2;
    dl[0] = l1; dl[HALFc] = l2;
}

// ------- transpose fp32 [Y,X] -> bf16 hi/lo [X,Y]; batched via z -------
__global__ __launch_bounds__(256) void transpose_convert_kernel(
    const float* __restrict__ in, long long inSb, long long inSh, int in_ld,
    __nv_bfloat16* __restrict__ ohi, __nv_bfloat16* __restrict__ olo,
    long long outSz, int Y)
{
    __shared__ float tile[32][33];
    int z = blockIdx.z, zb = z / NHc, zh = z % NHc;
    const float* inp = in + zb * inSb + zh * inSh;
    __nv_bfloat16* oh = ohi + (long long)z * outSz;
    __nv_bfloat16* ol = olo + (long long)z * outSz;
    int tx = threadIdx.x & 31, ty = threadIdx.x >> 5;
    int gx = blockIdx.x * 32 + tx;
    #pragma unroll
    for (int i = 0; i < 4; i++) {
        int gy = blockIdx.y * 32 + ty + i * 8;
        tile[ty + i * 8][tx] = inp[(size_t)gy * in_ld + gx];
    }
    __syncthreads();
    int ox = blockIdx.y * 32 + tx;
    #pragma unroll
    for (int i = 0; i < 4; i++) {
        int oy = blockIdx.x * 32 + ty + i * 8;
        __nv_bfloat16 h, l;
        split2(tile[tx][ty + i * 8], h, l);
        oh[(size_t)oy * Y + ox] = h;
        ol[(size_t)oy * Y + ox] = l;
    }
}

// ------- transpose fp32 [K,N] -> fp16 [N,K] -------
__global__ __launch_bounds__(256) void transpose_h16_kernel(
    const float* __restrict__ in, int in_ld,
    __half* __restrict__ outp, int K)
{
    __shared__ float tile[32][33];
    int tx = threadIdx.x & 31, ty = threadIdx.x >> 5;
    int gx = blockIdx.x * 32 + tx;
    #pragma unroll
    for (int i = 0; i < 4; i++) {
        int gy = blockIdx.y * 32 + ty + i * 8;
        tile[ty + i * 8][tx] = in[(size_t)gy * in_ld + gx];
    }
    __syncthreads();
    int ox = blockIdx.y * 32 + tx;
    #pragma unroll
    for (int i = 0; i < 4; i++) {
        int oy = blockIdx.x * 32 + ty + i * 8;
        outp[(size_t)oy * K + ox] = __float2half_rn(tile[tx][ty + i * 8]);
    }
}

// ------- causal softmax -> P bf16 hi/lo (zero-fill to 256 edge) -------
__global__ __launch_bounds__(256) void softmax_kernel(
    const float* __restrict__ scores,
    __nv_bfloat16* __restrict__ phi, __nv_bfloat16* __restrict__ plo)
{
    int i = blockIdx.x;
    int z = blockIdx.y;
    const float* row = scores + (size_t)z * Sc * Sc + (size_t)i * Sc;
    __nv_bfloat16* ph = phi + (size_t)z * Sc * Sc + (size_t)i * Sc;
    __nv_bfloat16* pl = plo + (size_t)z * Sc * Sc + (size_t)i * Sc;
    int nvalid = i + 1;

    float vals[8];
    float mx = -INFINITY;
    #pragma unroll
    for (int it = 0; it < 8; it++) {
        int j = threadIdx.x + it * 256;
        float v = (j < nvalid) ? row[j] : -INFINITY;
        vals[it] = v;
        mx = fmaxf(mx, v);
    }
    float M = block_reduce_max_256(mx);
    float sum = 0.f;
    #pragma unroll
    for (int it = 0; it < 8; it++) {
        int j = threadIdx.x + it * 256;
        float e = (j < nvalid) ? __expf(vals[it] - M) : 0.f;
        vals[it] = e;
        sum += e;
    }
    float tot = block_reduce_sum_256(sum);
    float inv = 1.f / tot;
    int zero_end = ((i >> 8) + 1) << 8;
    #pragma unroll
    for (int it = 0; it < 8; it++) {
        int j = threadIdx.x + it * 256;
        if (j < zero_end) {
            __nv_bfloat16 h, l;
            split2(vals[it] * inv, h, l);
            ph[j] = h; pl[j] = l;
        }
    }
}

// ---------------- SiLU(gate)*up -> fp16 ----------------
__global__ __launch_bounds__(256) void silu_h16_kernel(
    const float* __restrict__ gu, __half* __restrict__ act)
{
    int t = blockIdx.y;
    int i = blockIdx.x * 256 + threadIdx.x;
    float g = gu[(size_t)t * (2 * Ic) + i];
    float u = gu[(size_t)t * (2 * Ic) + Ic + i];
    act[(size_t)t * Ic + i] = __float2half_rn(g / (1.f + __expf(-g)) * u);
}

// ==================================================================
// bf16 3-pass GEMM (qkv + attention). R6 proven config:
// BM=256, BN=128, BK=32, 256 thr, 8 warps 64x64, 2-stage cp.async.
// ==================================================================
namespace gk {
constexpr int BM = 256, BN = 128, BK = 32, SROW = 40;
constexpr int AOFF_L = BM * SROW * 2;
constexpr int BOFF_H = 2 * AOFF_L;
constexpr int BOFF_L = BOFF_H + BN * SROW * 2;
constexpr int STAGE  = BOFF_L + BN * SROW * 2;
constexpr int SMEM_SZ = 2 * STAGE;              // 122880
}

template<bool CAUSAL, bool KLIM, bool H16OUT>
__global__ __launch_bounds__(256, 1) void hmma_gemm_kernel(
    const __nv_bfloat16* __restrict__ Ahi, const __nv_bfloat16* __restrict__ Alo,
    const __nv_bfloat16* __restrict__ Bhi, const __nv_bfloat16* __restrict__ Blo,
    float* __restrict__ Cf, __half* __restrict__ Ch,
    int K, int lda, int ldb, int ldc,
    long long sAb, long long sAh_, long long sBb, long long sBh_,
    long long sCb, long long sCh_, float alpha)
{
    using namespace gk;
    int rowBase = blockIdx.y * BM;
    int colBase = blockIdx.x * BN;
    if (CAUSAL && colBase > rowBase + BM - 1) return;

    extern __shared__ char smraw[];
    uint32_t sbase = smem_u32(smraw);

    int tid = threadIdx.x;
    int wid = tid >> 5, lane = tid & 31;
    int wm = wid & 3, wn = wid >> 2;

    int z = blockIdx.z, zb = z / NHc, zh = z % NHc;
    const __nv_bfloat16* Ah = Ahi + zb * sAb + zh * sAh_;
    const __nv_bfloat16* Al = Alo + zb * sAb + zh * sAh_;
    const __nv_bfloat16* Bh = Bhi + zb * sBb + zh * sBh_;
    const __nv_bfloat16* Bl = Blo + zb * sBb + zh * sBh_;

    int kEnd = KLIM ? min(K, rowBase + BM) : K;
    int nch  = kEnd / BK;

    float acc[4][8][4];
    #pragma unroll
    for (int a = 0; a < 4; a++)
        #pragma unroll
        for (int b = 0; b < 8; b++)
            #pragma unroll
            for (int c = 0; c < 4; c++) acc[a][b][c] = 0.f;

    int ar = tid >> 2, sg = (tid & 3) * 8;
    uint32_t soff = (uint32_t)(ar * SROW + sg) * 2;

    auto issue = [&](int c, int s) {
        int k0 = c * BK;
        uint32_t st = sbase + s * STAGE;
        #pragma unroll
        for (int it = 0; it < 4; it++) {
            int r = ar + it * 64;
            uint32_t o = soff + (uint32_t)(it * 64 * SROW) * 2;
            cp_async16(st + o,          Ah + (size_t)(rowBase + r) * lda + k0 + sg);
            cp_async16(st + AOFF_L + o, Al + (size_t)(rowBase + r) * lda + k0 + sg);
        }
        #pragma unroll
        for (int it = 0; it < 2; it++) {
            int r = ar + it * 64;
            uint32_t o = soff + (uint32_t)(it * 64 * SROW) * 2;
            cp_async16(st + BOFF_H + o, Bh + (size_t)(colBase + r) * ldb + k0 + sg);
            cp_async16(st + BOFF_L + o, Bl + (size_t)(colBase + r) * ldb + k0 + sg);
        }
    };

    int mat = lane >> 3, r8 = lane & 7;
    int a_row = (mat & 1) * 8 + r8, a_k = (mat >> 1) * 8;
    int b_n   = (mat >> 1) * 8 + r8, b_k = (mat & 1) * 8;

    issue(0, 0); CP_COMMIT();

    for (int c = 0; c < nch; ++c) {
        if (c + 1 < nch) { issue(c + 1, (c + 1) & 1); CP_COMMIT(); CP_WAIT(1); }
        else             { CP_WAIT(0); }
        __syncthreads();

        uint32_t st = sbase + (c & 1) * STAGE;
        #pragma unroll
        for (int ks = 0; ks < 2; ++ks) {
            uint32_t ah[4][4], al[4][4];
            #pragma unroll
            for (int mt = 0; mt < 4; ++mt) {
                uint32_t off = (uint32_t)((wm * 64 + mt * 16 + a_row) * SROW
                                          + ks * 16 + a_k) * 2;
                ldsm_x4(ah[mt], st + off);
                ldsm_x4(al[mt], st + AOFF_L + off);
            }
            #pragma unroll
            for (int nt = 0; nt < 4; ++nt) {
                uint32_t boff = (uint32_t)((wn * 64 + nt * 16 + b_n) * SROW
                                           + ks * 16 + b_k) * 2;
                uint32_t bh[4], bl[4];
                ldsm_x4(bh, st + BOFF_H + boff);
                ldsm_x4(bl, st + BOFF_L + boff);
                #pragma unroll
                for (int mt = 0; mt < 4; ++mt) {
                    #pragma unroll
                    for (int h2 = 0; h2 < 2; ++h2) {
                        mma_bf16(acc[mt][nt*2+h2], ah[mt], bh[2*h2], bh[2*h2+1]);
                        mma_bf16(acc[mt][nt*2+h2], ah[mt], bl[2*h2], bl[2*h2+1]);
                        mma_bf16(acc[mt][nt*2+h2], al[mt], bh[2*h2], bh[2*h2+1]);
                    }
                }
            }
        }
        __syncthreads();
    }

    float*  Cfz = Cf ? Cf + zb * sCb + zh * sCh_ : nullptr;
    __half* Chz = Ch ? Ch + zb * sCb + zh * sCh_ : nullptr;

    #pragma unroll
    for (int mt = 0; mt < 4; ++mt) {
        int r = rowBase + wm * 64 + mt * 16 + (lane >> 2);
        #pragma unroll
        for (int j8 = 0; j8 < 8; ++j8) {
            int cc = colBase + wn * 64 + j8 * 8 + 2 * (lane & 3);
            float v0 = acc[mt][j8][0] * alpha;
            float v1 = acc[mt][j8][1] * alpha;
            float v2 = acc[mt][j8][2] * alpha;
            float v3 = acc[mt][j8][3] * alpha;
            if (!H16OUT) {
                *(float2*)(Cfz + (size_t)r * ldc + cc)       = make_float2(v0, v1);
                *(float2*)(Cfz + (size_t)(r + 8) * ldc + cc) = make_float2(v2, v3);
            } else {
                *(__half2*)(Chz + (size_t)r * ldc + cc) =
                    __half2(__float2half_rn(v0), __float2half_rn(v1));
                *(__half2*)(Chz + (size_t)(r + 8) * ldc + cc) =
                    __half2(__float2half_rn(v2), __float2half_rn(v3));
            }
        }
    }
}

// ==================================================================
// fp16 1-pass GEMM (o/gate-up/down): C = A@B^T [+ADD].
// A:[M,K], B:[N,K] fp16 K-major. BM=128, BN=128, BK=32, 256 thr,
// 8 warps in 4x2 grid of 32x64 tiles (exact 128x128 cover),
// 3-stage cp.async, 2 CTAs/SM.
// ==================================================================
namespace hk {
constexpr int BM = 128, BN = 128, BK = 32, SROW = 40;
constexpr int BOFF  = BM * SROW * 2;            // 10240
constexpr int STAGE = BOFF + BN * SROW * 2;     // 20480
constexpr int NSTG  = 3;
constexpr int SMEM_SZ = NSTG * STAGE;           // 61440
}

template<bool ADDC>
__global__ __launch_bounds__(256, 2) void h16_gemm_kernel(
    const __half* __restrict__ A, const __half* __restrict__ B,
    float* __restrict__ C, const float* __restrict__ ADDp,
    int K, int ldc)
{
    using namespace hk;
    int rowBase = blockIdx.y * BM;
    int colBase = blockIdx.x * BN;

    extern __shared__ char smraw[];
    uint32_t sbase = smem_u32(smraw);

    int tid = threadIdx.x;
    int wid = tid >> 5, lane = tid & 31;
    int wm = wid & 3, wn = wid >> 2;              // 4m x 2n grid, 32x64 tiles

    int nch = K / BK;

    float acc[2][8][4];
    #pragma unroll
    for (int a = 0; a < 2; a++)
        #pragma unroll
        for (int b = 0; b < 8; b++)
            #pragma unroll
            for (int c = 0; c < 4; c++) acc[a][b][c] = 0.f;

    int ar = tid >> 2, sg = (tid & 3) * 8;        // ar in [0,64)
    uint32_t soff = (uint32_t)(ar * SROW + sg) * 2;

    auto issue = [&](int c) {
        int k0 = c * BK;
        uint32_t st = sbase + (c % NSTG) * STAGE;
        #pragma unroll
        for (int it = 0; it < 2; it++) {          // A: 128 rows
            int r = ar + it * 64;
            uint32_t o = soff + (uint32_t)(it * 64 * SROW) * 2;
            cp_async16(st + o, A + (size_t)(rowBase + r) * K + k0 + sg);
        }
        #pragma unroll
        for (int it = 0; it < 2; it++) {          // B: 128 rows
            int r = ar + it * 64;
            uint32_t o = soff + (uint32_t)(it * 64 * SROW) * 2;
            cp_async16(st + BOFF + o, B + (size_t)(colBase + r) * K + k0 + sg);
        }
    };

    int mat = lane >> 3, r8 = lane & 7;
    int a_row = (mat & 1) * 8 + r8, a_k = (mat >> 1) * 8;
    int b_n   = (mat >> 1) * 8 + r8, b_k = (mat & 1) * 8;

    issue(0); CP_COMMIT();
    if (nch > 1) { issue(1); CP_COMMIT(); } else { CP_COMMIT(); }

    for (int c = 0; c < nch; ++c) {
        if (c + 2 < nch) issue(c + 2);
        CP_COMMIT();
        CP_WAIT(2);
        __syncthreads();

        uint32_t st = sbase + (c % NSTG) * STAGE;
        #pragma unroll
        for (int ks = 0; ks < 2; ++ks) {
            uint32_t af[2][4];
            #pragma unroll
            for (int mt = 0; mt < 2; ++mt) {
                uint32_t off = (uint32_t)((wm * 32 + mt * 16 + a_row) * SROW
                                          + ks * 16 + a_k) * 2;
                ldsm_x4(af[mt], st + off);
            }
            #pragma unroll
            for (int nt = 0; nt < 4; ++nt) {
                uint32_t boff = (uint32_t)((wn * 64 + nt * 16 + b_n) * SROW
                                           + ks * 16 + b_k) * 2;
                uint32_t bf[4];
                ldsm_x4(bf, st + BOFF + boff);
                #pragma unroll
                for (int mt = 0; mt < 2; ++mt) {
                    #pragma unroll
                    for (int h2 = 0; h2 < 2; ++h2)
                        mma_f16(acc[mt][nt*2+h2], af[mt], bf[2*h2], bf[2*h2+1]);
                }
            }
        }
        __syncthreads();
    }

    #pragma unroll
    for (int mt = 0; mt < 2; ++mt) {
        int r = rowBase + wm * 32 + mt * 16 + (lane >> 2);
        #pragma unroll
        for (int j8 = 0; j8 < 8; ++j8) {
            int cc = colBase + wn * 64 + j8 * 8 + 2 * (lane & 3);
            float v0 = acc[mt][j8][0], v1 = acc[mt][j8][1];
            float v2 = acc[mt][j8][2], v3 = acc[mt][j8][3];
            if (ADDC) {
                float2 a0 = *(const float2*)(ADDp + (size_t)r * ldc + cc);
                float2 a1 = *(const float2*)(ADDp + (size_t)(r + 8) * ldc + cc);
                v0 += a0.x; v1 += a0.y; v2 += a1.x; v3 += a1.y;
            }
            *(float2*)(C + (size_t)r * ldc + cc)       = make_float2(v0, v1);
            *(float2*)(C + (size_t)(r + 8) * ldc + cc) = make_float2(v2, v3);
        }
    }
}

// ---------------- host launcher ----------------
extern "C" void kernel_launch(void* const* d_in, const int* in_sizes, int n_in,
                              void* d_out, int out_size)
{
    const float* hs    = (const float*)d_in[0];
    const float* resid = (const float*)d_in[1];
    const float* cosp  = (const float*)d_in[2];
    const float* sinp  = (const float*)d_in[3];
    const float* w_qkv = (const float*)d_in[4];
    const float* w_o   = (const float*)d_in[5];
    const float* w_gu  = (const float*)d_in[6];
    const float* w_dn  = (const float*)d_in[7];
    const float* ln1   = (const float*)d_in[8];
    const float* ln2   = (const float*)d_in[9];

    float* out     = (float*)d_out;
    float* mlp_out = out;
    float* res2    = out + (size_t)Tc * Hc;

    float *p_res1, *p_qkv, *p_scores, *p_gu;
    cudaGetSymbolAddress((void**)&p_res1,   g_res1);
    cudaGetSymbolAddress((void**)&p_qkv,    g_qkv);
    cudaGetSymbolAddress((void**)&p_scores, g_scores);
    cudaGetSymbolAddress((void**)&p_gu,     g_gu);
    __nv_bfloat16 *nh,*nl,*qh,*ql,*kh,*kl,*vth,*vtl,*ph,*pl,*wqh,*wql;
    cudaGetSymbolAddress((void**)&nh,  g_n_hi);  cudaGetSymbolAddress((void**)&nl,  g_n_lo);
    cudaGetSymbolAddress((void**)&qh,  g_q_hi);  cudaGetSymbolAddress((void**)&ql,  g_q_lo);
    cudaGetSymbolAddress((void**)&kh,  g_k_hi);  cudaGetSymbolAddress((void**)&kl,  g_k_lo);
    cudaGetSymbolAddress((void**)&vth, g_vt_hi); cudaGetSymbolAddress((void**)&vtl, g_vt_lo);
    cudaGetSymbolAddress((void**)&ph,  g_p_hi);  cudaGetSymbolAddress((void**)&pl,  g_p_lo);
    cudaGetSymbolAddress((void**)&wqh, g_wqkv_hi); cudaGetSymbolAddress((void**)&wql, g_wqkv_lo);
    __half *ath,*n2h,*ach,*woh,*wgh,*wdh;
    cudaGetSymbolAddress((void**)&ath, g_at_h);
    cudaGetSymbolAddress((void**)&n2h, g_n2_h);
    cudaGetSymbolAddress((void**)&ach, g_ac_h);
    cudaGetSymbolAddress((void**)&woh, g_wo_h);
    cudaGetSymbolAddress((void**)&wgh, g_wgu_h);
    cudaGetSymbolAddress((void**)&wdh, g_wdn_h);

    cudaFuncSetAttribute(hmma_gemm_kernel<false,false,false>, cudaFuncAttributeMaxDynamicSharedMemorySize, gk::SMEM_SZ);
    cudaFuncSetAttribute(hmma_gemm_kernel<true, false,false>, cudaFuncAttributeMaxDynamicSharedMemorySize, gk::SMEM_SZ);
    cudaFuncSetAttribute(hmma_gemm_kernel<false,true, true >, cudaFuncAttributeMaxDynamicSharedMemorySize, gk::SMEM_SZ);
    cudaFuncSetAttribute(h16_gemm_kernel<false>, cudaFuncAttributeMaxDynamicSharedMemorySize, hk::SMEM_SZ);
    cudaFuncSetAttribute(h16_gemm_kernel<true>,  cudaFuncAttributeMaxDynamicSharedMemorySize, hk::SMEM_SZ);

    // weight prep: wqkv -> bf16 2-plane; wo/wgu/wdn -> fp16 1-plane
    transpose_convert_kernel<<<dim3(3*Hc/32, Hc/32, 1), 256>>>(w_qkv, 0, 0, 3*Hc, wqh, wql, 0, Hc);
    transpose_h16_kernel<<<dim3(Hc/32,   Hc/32), 256>>>(w_o,  Hc,   woh, Hc);
    transpose_h16_kernel<<<dim3(2*Ic/32, Hc/32), 256>>>(w_gu, 2*Ic, wgh, Hc);
    transpose_h16_kernel<<<dim3(Hc/32,   Ic/32), 256>>>(w_dn, Hc,   wdh, Ic);

    // 1) res1 + RMSNorm -> bf16 planes
    add_rmsnorm_kernel<<<Tc, 256>>>(hs, resid, ln1, p_res1, nh, nl, nullptr);

    // 2) qkv = normed @ w_qkv (bf16 3-pass, fp32 out)
    hmma_gemm_kernel<false,false,false><<<dim3(3*Hc/128, Tc/256, 1), 256, gk::SMEM_SZ>>>(
        nh, nl, wqh, wql, p_qkv, nullptr,
        Hc, Hc, Hc, 3*Hc, 0,0,0,0,0,0, 1.f);

    // 3) RoPE + V transpose
    rope_kernel<<<(Tc*2*NHc*HALFc)/256, 256>>>(p_qkv, cosp, sinp, qh, ql, kh, kl);
    transpose_convert_kernel<<<dim3(HDc/32, Sc/32, Bc*NHc), 256>>>(
        p_qkv + 2*Hc, (long long)Sc*3*Hc, HDc, 3*Hc, vth, vtl, (long long)HDc*Sc, Sc);

    // 4) scores = scale * Q @ K^T (causal)
    hmma_gemm_kernel<true,false,false><<<dim3(Sc/128, Sc/256, Bc*NHc), 256, gk::SMEM_SZ>>>(
        qh, ql, kh, kl, p_scores, nullptr,
        HDc, Hc, Hc, Sc,
        (long long)Sc*Hc, HDc, (long long)Sc*Hc, HDc,
        (long long)NHc*Sc*Sc, (long long)Sc*Sc, SCALEc);

    // 5) softmax -> P planes
    softmax_kernel<<<dim3(Sc, Bc*NHc), 256>>>(p_scores, ph, pl);

    // 6) attn = P @ V (K-limited) -> fp16 plane [T,H]
    hmma_gemm_kernel<false,true,true><<<dim3(1, Sc/256, Bc*NHc), 256, gk::SMEM_SZ>>>(
        ph, pl, vth, vtl, nullptr, ath,
        Sc, Sc, Sc, Hc,
        (long long)NHc*Sc*Sc, (long long)Sc*Sc,
        (long long)NHc*HDc*Sc, (long long)HDc*Sc,
        (long long)Sc*Hc, HDc, 1.f);

    // 7) res2 = attn @ w_o + res1 (fp16 1-pass, into output)
    h16_gemm_kernel<true><<<dim3(Hc/128, Tc/128), 256, hk::SMEM_SZ>>>(
        ath, woh, res2, p_res1, Hc, Hc);

    // 8) RMSNorm(res2) -> fp16 plane
    add_rmsnorm_kernel<<<Tc, 256>>>(res2, nullptr, ln2, nullptr, nullptr, nullptr, n2h);

    // 9) gu = normed2 @ w_gate_up (fp16 1-pass)
    h16_gemm_kernel<false><<<dim3(2*Ic/128, Tc/128), 256, hk::SMEM_SZ>>>(
        n2h, wgh, p_gu, nullptr, Hc, 2*Ic);

    // 10) silu*up -> fp16 plane
    silu_h16_kernel<<<dim3(Ic/256, Tc), 256>>>(p_gu, ach);

    // 11) mlp_out = act @ w_down (fp16 1-pass, into output)
    h16_gemm_kernel<false><<<dim3(Hc/128, Tc/128), 256, hk::SMEM_SZ>>>(
        ach, wdh, mlp_out, nullptr, Ic, Hc);
}

// round 13
// speedup vs baseline: 4.7298x; 1.0506x over previous
#include <cuda_runtime.h>
#include <cuda_bf16.h>
#include <cuda_fp16.h>
#include <math.h>
#include <stdint.h>

namespace {
constexpr int Bc  = 2;
constexpr int Sc  = 2048;
constexpr int Hc  = 4096;
constexpr int NHc = 32;
constexpr int HDc = 128;
constexpr int Ic  = 11008;
constexpr int Tc  = Bc * Sc;
constexpr int HALFc = HDc / 2;
constexpr float EPSc = 1e-6f;
constexpr float SCALEc = 0.08838834764831843f;
}

// ---------------- device scratch ----------------
__device__ float g_res1  [(size_t)Tc * Hc];
__device__ float g_qkv   [(size_t)Tc * 3 * Hc];
__device__ float g_scores[(size_t)Bc * NHc * Sc * Sc];

__device__ __nv_bfloat16 g_n_hi [(size_t)Tc * Hc],  g_n_lo [(size_t)Tc * Hc];
__device__ __nv_bfloat16 g_q_hi [(size_t)Tc * Hc],  g_q_lo [(size_t)Tc * Hc];
__device__ __nv_bfloat16 g_k_hi [(size_t)Tc * Hc],  g_k_lo [(size_t)Tc * Hc];
__device__ __nv_bfloat16 g_wqkv_hi[(size_t)Hc * 3 * Hc], g_wqkv_lo[(size_t)Hc * 3 * Hc];

// fp16 single-plane tensors
__device__ __half g_p_h  [(size_t)Bc * NHc * Sc * Sc];   // softmax probs
__device__ __half g_vt_h [(size_t)Tc * Hc];              // V transposed [z][HD][S]
__device__ __half g_at_h [(size_t)Tc * Hc];
__device__ __half g_n2_h [(size_t)Tc * Hc];
__device__ __half g_ac_h [(size_t)Tc * Ic];
__device__ __half g_wo_h [(size_t)Hc * Hc];
__device__ __half g_wgu_h[(size_t)2 * Ic * Hc];          // interleaved gate/up rows
__device__ __half g_wdn_h[(size_t)Hc * Ic];

// ---------------- helpers ----------------
__device__ __forceinline__ uint32_t smem_u32(const void* p) {
    return (uint32_t)__cvta_generic_to_shared(p);
}
__device__ __forceinline__ void ldsm_x4(uint32_t (&r)[4], uint32_t addr) {
    asm volatile("ldmatrix.sync.aligned.m8n8.x4.shared.b16 {%0,%1,%2,%3}, [%4];"
                 : "=r"(r[0]), "=r"(r[1]), "=r"(r[2]), "=r"(r[3]) : "r"(addr));
}
__device__ __forceinline__ void mma_bf16(float (&d)[4], const uint32_t (&a)[4],
                                         uint32_t b0, uint32_t b1) {
    asm volatile("mma.sync.aligned.m16n8k16.row.col.f32.bf16.bf16.f32 "
        "{%0,%1,%2,%3}, {%4,%5,%6,%7}, {%8,%9}, {%0,%1,%2,%3};"
        : "+f"(d[0]), "+f"(d[1]), "+f"(d[2]), "+f"(d[3])
        : "r"(a[0]), "r"(a[1]), "r"(a[2]), "r"(a[3]), "r"(b0), "r"(b1));
}
__device__ __forceinline__ void mma_f16(float (&d)[4], const uint32_t (&a)[4],
                                        uint32_t b0, uint32_t b1) {
    asm volatile("mma.sync.aligned.m16n8k16.row.col.f32.f16.f16.f32 "
        "{%0,%1,%2,%3}, {%4,%5,%6,%7}, {%8,%9}, {%0,%1,%2,%3};"
        : "+f"(d[0]), "+f"(d[1]), "+f"(d[2]), "+f"(d[3])
        : "r"(a[0]), "r"(a[1]), "r"(a[2]), "r"(a[3]), "r"(b0), "r"(b1));
}
__device__ __forceinline__ void cp_async16(uint32_t dst, const void* src) {
    asm volatile("cp.async.cg.shared.global [%0], [%1], 16;" :: "r"(dst), "l"(src));
}
#define CP_COMMIT() asm volatile("cp.async.commit_group;" ::: "memory")
#define CP_WAIT(n)  asm volatile("cp.async.wait_group %0;" :: "n"(n) : "memory")
__device__ __forceinline__ void split2(float v, __nv_bfloat16& h, __nv_bfloat16& l) {
    h = __float2bfloat16(v);
    l = __float2bfloat16(v - __bfloat162float(h));
}

// ---------------- block reductions (256 thr) ----------------
__device__ __forceinline__ float block_reduce_sum_256(float v) {
    #pragma unroll
    for (int o = 16; o > 0; o >>= 1) v += __shfl_down_sync(0xffffffffu, v, o);
    __shared__ float red[8];
    int w = threadIdx.x >> 5, l = threadIdx.x & 31;
    if (l == 0) red[w] = v;
    __syncthreads();
    if (w == 0) {
        float x = (l < 8) ? red[l] : 0.f;
        #pragma unroll
        for (int o = 4; o > 0; o >>= 1) x += __shfl_down_sync(0xffu, x, o);
        if (l == 0) red[0] = x;
    }
    __syncthreads();
    float r = red[0];
    __syncthreads();
    return r;
}
__device__ __forceinline__ float block_reduce_max_256(float v) {
    #pragma unroll
    for (int o = 16; o > 0; o >>= 1) v = fmaxf(v, __shfl_down_sync(0xffffffffu, v, o));
    __shared__ float red[8];
    int w = threadIdx.x >> 5, l = threadIdx.x & 31;
    if (l == 0) red[w] = v;
    __syncthreads();
    if (w == 0) {
        float x = (l < 8) ? red[l] : -INFINITY;
        #pragma unroll
        for (int o = 4; o > 0; o >>= 1) x = fmaxf(x, __shfl_down_sync(0xffu, x, o));
        if (l == 0) red[0] = x;
    }
    __syncthreads();
    float r = red[0];
    __syncthreads();
    return r;
}

// ------- add + RMSNorm -> bf16 hi/lo OR fp16 single plane -------
__global__ __launch_bounds__(256) void add_rmsnorm_kernel(
    const float* __restrict__ a, const float* __restrict__ b,
    const float* __restrict__ w, float* __restrict__ sum_out,
    __nv_bfloat16* __restrict__ ohi, __nv_bfloat16* __restrict__ olo,
    __half* __restrict__ oh16)
{
    int row = blockIdx.x;
    const float4* a4 = (const float4*)(a + (size_t)row * Hc);
    const float4* b4 = b ? (const float4*)(b + (size_t)row * Hc) : nullptr;
    const float4* w4 = (const float4*)w;
    float4* s4 = sum_out ? (float4*)(sum_out + (size_t)row * Hc) : nullptr;

    float4 v[4];
    float ss = 0.f;
    #pragma unroll
    for (int it = 0; it < 4; it++) {
        int idx = threadIdx.x + it * 256;
        float4 va = a4[idx];
        if (b4) { float4 vb = b4[idx]; va.x += vb.x; va.y += vb.y; va.z += vb.z; va.w += vb.w; }
        v[it] = va;
        ss += va.x * va.x + va.y * va.y + va.z * va.z + va.w * va.w;
    }
    float tot = block_reduce_sum_256(ss);
    float scale = rsqrtf(tot / (float)Hc + EPSc);
    #pragma unroll
    for (int it = 0; it < 4; it++) {
        int idx = threadIdx.x + it * 256;
        if (s4) s4[idx] = v[it];
        float4 vw = w4[idx];
        float y0 = v[it].x * scale * vw.x, y1 = v[it].y * scale * vw.y;
        float y2 = v[it].z * scale * vw.z, y3 = v[it].w * scale * vw.w;
        if (oh16) {
            __half2* o2 = (__half2*)(oh16 + (size_t)row * Hc);
            o2[idx*2]   = __half2(__float2half_rn(y0), __float2half_rn(y1));
            o2[idx*2+1] = __half2(__float2half_rn(y2), __float2half_rn(y3));
        } else {
            __nv_bfloat162* oh2 = (__nv_bfloat162*)(ohi + (size_t)row * Hc);
            __nv_bfloat162* ol2 = (__nv_bfloat162*)(olo + (size_t)row * Hc);
            __nv_bfloat16 h0,l0,h1,l1,h2,l2,h3,l3;
            split2(y0,h0,l0); split2(y1,h1,l1); split2(y2,h2,l2); split2(y3,h3,l3);
            oh2[idx*2]   = __nv_bfloat162(h0,h1);
            oh2[idx*2+1] = __nv_bfloat162(h2,h3);
            ol2[idx*2]   = __nv_bfloat162(l0,l1);
            ol2[idx*2+1] = __nv_bfloat162(l2,l3);
        }
    }
}

// ---------------- RoPE: fp32 qkv -> Q/K bf16 hi/lo ----------------
__global__ __launch_bounds__(256) void rope_kernel(
    const float* __restrict__ qkv, const float* __restrict__ cosp,
    const float* __restrict__ sinp,
    __nv_bfloat16* __restrict__ qhi, __nv_bfloat16* __restrict__ qlo,
    __nv_bfloat16* __restrict__ khi, __nv_bfloat16* __restrict__ klo)
{
    int idx = blockIdx.x * 256 + threadIdx.x;
    int d = idx & (HALFc - 1);
    int h = (idx >> 6) & (NHc - 1);
    int m = (idx >> 11) & 1;
    int t = idx >> 12;
    const float* p = qkv + (size_t)t * (3 * Hc) + m * Hc + h * HDc + d;
    float x1 = p[0], x2 = p[HALFc];
    float c = cosp[(size_t)t * HALFc + d];
    float s = sinp[(size_t)t * HALFc + d];
    float y1 = x1 * c - x2 * s;
    float y2 = x1 * s + x2 * c;
    __nv_bfloat16* dh = (m ? khi : qhi) + (size_t)t * Hc + h * HDc + d;
    __nv_bfloat16* dl = (m ? klo : qlo) + (size_t)t * Hc + h * HDc + d;
    __nv_bfloat16 h1, l1, h2, l2;
    split2(y1, h1, l1); split2(y2, h2, l2);
    dh[0] = h1; dh[HALFc] = h2;
    dl[0] = l1; dl[HALFc] = l2;
}

// ------- transpose fp32 [Y,X] -> bf16 hi/lo [X,Y] (wqkv only) -------
__global__ __launch_bounds__(256) void transpose_convert_kernel(
    const float* __restrict__ in, int in_ld,
    __nv_bfloat16* __restrict__ ohi, __nv_bfloat16* __restrict__ olo, int Y)
{
    __shared__ float tile[32][33];
    int tx = threadIdx.x & 31, ty = threadIdx.x >> 5;
    int gx = blockIdx.x * 32 + tx;
    #pragma unroll
    for (int i = 0; i < 4; i++) {
        int gy = blockIdx.y * 32 + ty + i * 8;
        tile[ty + i * 8][tx] = in[(size_t)gy * in_ld + gx];
    }
    __syncthreads();
    int ox = blockIdx.y * 32 + tx;
    #pragma unroll
    for (int i = 0; i < 4; i++) {
        int oy = blockIdx.x * 32 + ty + i * 8;
        __nv_bfloat16 h, l;
        split2(tile[tx][ty + i * 8], h, l);
        ohi[(size_t)oy * Y + ox] = h;
        olo[(size_t)oy * Y + ox] = l;
    }
}

// ------- transpose fp32 [Y,X] -> fp16 [X,Y]; batched; optional interleave -------
// interHalf>0: output row oy remapped (oy<interHalf -> 2*oy else 2*(oy-interHalf)+1)
__global__ __launch_bounds__(256) void transpose_h16_kernel(
    const float* __restrict__ in, long long inSb, long long inSh, int in_ld,
    __half* __restrict__ outp, long long outSz, int K, int interHalf)
{
    __shared__ float tile[32][33];
    int z = blockIdx.z, zb = z / NHc, zh = z % NHc;
    const float* inp = in + zb * inSb + zh * inSh;
    __half* op = outp + (long long)z * outSz;
    int tx = threadIdx.x & 31, ty = threadIdx.x >> 5;
    int gx = blockIdx.x * 32 + tx;
    #pragma unroll
    for (int i = 0; i < 4; i++) {
        int gy = blockIdx.y * 32 + ty + i * 8;
        tile[ty + i * 8][tx] = inp[(size_t)gy * in_ld + gx];
    }
    __syncthreads();
    int ox = blockIdx.y * 32 + tx;
    #pragma unroll
    for (int i = 0; i < 4; i++) {
        int oy = blockIdx.x * 32 + ty + i * 8;
        int oyr = interHalf ? ((oy < interHalf) ? 2 * oy : 2 * (oy - interHalf) + 1) : oy;
        op[(size_t)oyr * K + ox] = __float2half_rn(tile[tx][ty + i * 8]);
    }
}

// ------- causal softmax -> P fp16 (zero-fill to 128-aligned edge) -------
__global__ __launch_bounds__(256) void softmax_kernel(
    const float* __restrict__ scores, __half* __restrict__ ph)
{
    int i = blockIdx.x;
    int z = blockIdx.y;
    const float* row = scores + (size_t)z * Sc * Sc + (size_t)i * Sc;
    __half* pr = ph + (size_t)z * Sc * Sc + (size_t)i * Sc;
    int nvalid = i + 1;

    float vals[8];
    float mx = -INFINITY;
    #pragma unroll
    for (int it = 0; it < 8; it++) {
        int j = threadIdx.x + it * 256;
        float v = (j < nvalid) ? row[j] : -INFINITY;
        vals[it] = v;
        mx = fmaxf(mx, v);
    }
    float M = block_reduce_max_256(mx);
    float sum = 0.f;
    #pragma unroll
    for (int it = 0; it < 8; it++) {
        int j = threadIdx.x + it * 256;
        float e = (j < nvalid) ? __expf(vals[it] - M) : 0.f;
        vals[it] = e;
        sum += e;
    }
    float tot = block_reduce_sum_256(sum);
    float inv = 1.f / tot;
    int zero_end = ((i >> 7) + 1) << 7;   // 128-aligned (PV BM=128 K-limit)
    #pragma unroll
    for (int it = 0; it < 8; it++) {
        int j = threadIdx.x + it * 256;
        if (j < zero_end) pr[j] = __float2half_rn(vals[it] * inv);
    }
}

// ==================================================================
// bf16 3-pass GEMM (qkv + QK^T). R6 proven config:
// BM=256, BN=128, BK=32, 256 thr, 8 warps 64x64, 2-stage cp.async.
// ==================================================================
namespace gk {
constexpr int BM = 256, BN = 128, BK = 32, SROW = 40;
constexpr int AOFF_L = BM * SROW * 2;
constexpr int BOFF_H = 2 * AOFF_L;
constexpr int BOFF_L = BOFF_H + BN * SROW * 2;
constexpr int STAGE  = BOFF_L + BN * SROW * 2;
constexpr int SMEM_SZ = 2 * STAGE;              // 122880
}

template<bool CAUSAL>
__global__ __launch_bounds__(256, 1) void hmma_gemm_kernel(
    const __nv_bfloat16* __restrict__ Ahi, const __nv_bfloat16* __restrict__ Alo,
    const __nv_bfloat16* __restrict__ Bhi, const __nv_bfloat16* __restrict__ Blo,
    float* __restrict__ Cf,
    int K, int lda, int ldb, int ldc,
    long long sAb, long long sAh_, long long sBb, long long sBh_,
    long long sCb, long long sCh_, float alpha)
{
    using namespace gk;
    int rowBase = blockIdx.y * BM;
    int colBase = blockIdx.x * BN;
    if (CAUSAL && colBase > rowBase + BM - 1) return;

    extern __shared__ char smraw[];
    uint32_t sbase = smem_u32(smraw);

    int tid = threadIdx.x;
    int wid = tid >> 5, lane = tid & 31;
    int wm = wid & 3, wn = wid >> 2;

    int z = blockIdx.z, zb = z / NHc, zh = z % NHc;
    const __nv_bfloat16* Ah = Ahi + zb * sAb + zh * sAh_;
    const __nv_bfloat16* Al = Alo + zb * sAb + zh * sAh_;
    const __nv_bfloat16* Bh = Bhi + zb * sBb + zh * sBh_;
    const __nv_bfloat16* Bl = Blo + zb * sBb + zh * sBh_;

    int nch = K / BK;

    float acc[4][8][4];
    #pragma unroll
    for (int a = 0; a < 4; a++)
        #pragma unroll
        for (int b = 0; b < 8; b++)
            #pragma unroll
            for (int c = 0; c < 4; c++) acc[a][b][c] = 0.f;

    int ar = tid >> 2, sg = (tid & 3) * 8;
    uint32_t soff = (uint32_t)(ar * SROW + sg) * 2;

    auto issue = [&](int c, int s) {
        int k0 = c * BK;
        uint32_t st = sbase + s * STAGE;
        #pragma unroll
        for (int it = 0; it < 4; it++) {
            int r = ar + it * 64;
            uint32_t o = soff + (uint32_t)(it * 64 * SROW) * 2;
            cp_async16(st + o,          Ah + (size_t)(rowBase + r) * lda + k0 + sg);
            cp_async16(st + AOFF_L + o, Al + (size_t)(rowBase + r) * lda + k0 + sg);
        }
        #pragma unroll
        for (int it = 0; it < 2; it++) {
            int r = ar + it * 64;
            uint32_t o = soff + (uint32_t)(it * 64 * SROW) * 2;
            cp_async16(st + BOFF_H + o, Bh + (size_t)(colBase + r) * ldb + k0 + sg);
            cp_async16(st + BOFF_L + o, Bl + (size_t)(colBase + r) * ldb + k0 + sg);
        }
    };

    int mat = lane >> 3, r8 = lane & 7;
    int a_row = (mat & 1) * 8 + r8, a_k = (mat >> 1) * 8;
    int b_n   = (mat >> 1) * 8 + r8, b_k = (mat & 1) * 8;

    issue(0, 0); CP_COMMIT();

    for (int c = 0; c < nch; ++c) {
        if (c + 1 < nch) { issue(c + 1, (c + 1) & 1); CP_COMMIT(); CP_WAIT(1); }
        else             { CP_WAIT(0); }
        __syncthreads();

        uint32_t st = sbase + (c & 1) * STAGE;
        #pragma unroll
        for (int ks = 0; ks < 2; ++ks) {
            uint32_t ah[4][4], al[4][4];
            #pragma unroll
            for (int mt = 0; mt < 4; ++mt) {
                uint32_t off = (uint32_t)((wm * 64 + mt * 16 + a_row) * SROW
                                          + ks * 16 + a_k) * 2;
                ldsm_x4(ah[mt], st + off);
                ldsm_x4(al[mt], st + AOFF_L + off);
            }
            #pragma unroll
            for (int nt = 0; nt < 4; ++nt) {
                uint32_t boff = (uint32_t)((wn * 64 + nt * 16 + b_n) * SROW
                                           + ks * 16 + b_k) * 2;
                uint32_t bh[4], bl[4];
                ldsm_x4(bh, st + BOFF_H + boff);
                ldsm_x4(bl, st + BOFF_L + boff);
                #pragma unroll
                for (int mt = 0; mt < 4; ++mt) {
                    #pragma unroll
                    for (int h2 = 0; h2 < 2; ++h2) {
                        mma_bf16(acc[mt][nt*2+h2], ah[mt], bh[2*h2], bh[2*h2+1]);
                        mma_bf16(acc[mt][nt*2+h2], ah[mt], bl[2*h2], bl[2*h2+1]);
                        mma_bf16(acc[mt][nt*2+h2], al[mt], bh[2*h2], bh[2*h2+1]);
                    }
                }
            }
        }
        __syncthreads();
    }

    float* Cfz = Cf + zb * sCb + zh * sCh_;
    #pragma unroll
    for (int mt = 0; mt < 4; ++mt) {
        int r = rowBase + wm * 64 + mt * 16 + (lane >> 2);
        #pragma unroll
        for (int j8 = 0; j8 < 8; ++j8) {
            int cc = colBase + wn * 64 + j8 * 8 + 2 * (lane & 3);
            *(float2*)(Cfz + (size_t)r * ldc + cc) =
                make_float2(acc[mt][j8][0] * alpha, acc[mt][j8][1] * alpha);
            *(float2*)(Cfz + (size_t)(r + 8) * ldc + cc) =
                make_float2(acc[mt][j8][2] * alpha, acc[mt][j8][3] * alpha);
        }
    }
}

// ==================================================================
// fp16 1-pass GEMM: C = A@B^T [+ADD]. BM=128, BN=128, BK=32, 256 thr,
// 8 warps 4x2 grid of 32x64 tiles, 3-stage cp.async, 2 CTAs/SM.
// KLIM: K-limit to rowBase+BM (PV). H16OUT: fp16 out. SILU: fused
// silu(even)*odd epilogue writing fp16 at col cc/2 (ldc = Ic).
// Batched via blockIdx.z strides.
// ==================================================================
namespace hk {
constexpr int BM = 128, BN = 128, BK = 32, SROW = 40;
constexpr int BOFF  = BM * SROW * 2;            // 10240
constexpr int STAGE = BOFF + BN * SROW * 2;     // 20480
constexpr int NSTG  = 3;
constexpr int SMEM_SZ = NSTG * STAGE;           // 61440
}

template<bool ADDC, bool KLIM, bool H16OUT, bool SILU>
__global__ __launch_bounds__(256, 2) void h16_gemm_kernel(
    const __half* __restrict__ A, const __half* __restrict__ B,
    float* __restrict__ Cf, __half* __restrict__ Ch,
    const float* __restrict__ ADDp,
    int K, int lda, int ldb, int ldc,
    long long sAb, long long sAh_, long long sBb, long long sBh_,
    long long sCb, long long sCh_)
{
    using namespace hk;
    int rowBase = blockIdx.y * BM;
    int colBase = blockIdx.x * BN;

    extern __shared__ char smraw[];
    uint32_t sbase = smem_u32(smraw);

    int tid = threadIdx.x;
    int wid = tid >> 5, lane = tid & 31;
    int wm = wid & 3, wn = wid >> 2;

    int z = blockIdx.z, zb = z / NHc, zh = z % NHc;
    const __half* Az = A + zb * sAb + zh * sAh_;
    const __half* Bz = B + zb * sBb + zh * sBh_;

    int kEnd = KLIM ? min(K, rowBase + BM) : K;
    int nch  = kEnd / BK;

    float acc[2][8][4];
    #pragma unroll
    for (int a = 0; a < 2; a++)
        #pragma unroll
        for (int b = 0; b < 8; b++)
            #pragma unroll
            for (int c = 0; c < 4; c++) acc[a][b][c] = 0.f;

    int ar = tid >> 2, sg = (tid & 3) * 8;
    uint32_t soff = (uint32_t)(ar * SROW + sg) * 2;

    auto issue = [&](int c) {
        int k0 = c * BK;
        uint32_t st = sbase + (c % NSTG) * STAGE;
        #pragma unroll
        for (int it = 0; it < 2; it++) {
            int r = ar + it * 64;
            uint32_t o = soff + (uint32_t)(it * 64 * SROW) * 2;
            cp_async16(st + o,        Az + (size_t)(rowBase + r) * lda + k0 + sg);
            cp_async16(st + BOFF + o, Bz + (size_t)(colBase + r) * ldb + k0 + sg);
        }
    };

    int mat = lane >> 3, r8 = lane & 7;
    int a_row = (mat & 1) * 8 + r8, a_k = (mat >> 1) * 8;
    int b_n   = (mat >> 1) * 8 + r8, b_k = (mat & 1) * 8;

    issue(0); CP_COMMIT();
    if (nch > 1) { issue(1); CP_COMMIT(); } else { CP_COMMIT(); }

    for (int c = 0; c < nch; ++c) {
        if (c + 2 < nch) issue(c + 2);
        CP_COMMIT();
        CP_WAIT(2);
        __syncthreads();

        uint32_t st = sbase + (c % NSTG) * STAGE;
        #pragma unroll
        for (int ks = 0; ks < 2; ++ks) {
            uint32_t af[2][4];
            #pragma unroll
            for (int mt = 0; mt < 2; ++mt) {
                uint32_t off = (uint32_t)((wm * 32 + mt * 16 + a_row) * SROW
                                          + ks * 16 + a_k) * 2;
                ldsm_x4(af[mt], st + off);
            }
            #pragma unroll
            for (int nt = 0; nt < 4; ++nt) {
                uint32_t boff = (uint32_t)((wn * 64 + nt * 16 + b_n) * SROW
                                           + ks * 16 + b_k) * 2;
                uint32_t bf[4];
                ldsm_x4(bf, st + BOFF + boff);
                #pragma unroll
                for (int mt = 0; mt < 2; ++mt) {
                    #pragma unroll
                    for (int h2 = 0; h2 < 2; ++h2)
                        mma_f16(acc[mt][nt*2+h2], af[mt], bf[2*h2], bf[2*h2+1]);
                }
            }
        }
        __syncthreads();
    }

    float*  Cfz = Cf ? Cf + zb * sCb + zh * sCh_ : nullptr;
    __half* Chz = Ch ? Ch + zb * sCb + zh * sCh_ : nullptr;
    const float* ADz = ADDp ? ADDp + zb * sCb + zh * sCh_ : nullptr;

    #pragma unroll
    for (int mt = 0; mt < 2; ++mt) {
        int r = rowBase + wm * 32 + mt * 16 + (lane >> 2);
        #pragma unroll
        for (int j8 = 0; j8 < 8; ++j8) {
            int cc = colBase + wn * 64 + j8 * 8 + 2 * (lane & 3);
            float v0 = acc[mt][j8][0], v1 = acc[mt][j8][1];
            float v2 = acc[mt][j8][2], v3 = acc[mt][j8][3];
            if (SILU) {
                // (v0,v1) = (gate,up) at n = cc/2 for row r; (v2,v3) same for r+8
                float a0 = v0 / (1.f + __expf(-v0)) * v1;
                float a1 = v2 / (1.f + __expf(-v2)) * v3;
                Chz[(size_t)r * ldc + (cc >> 1)]       = __float2half_rn(a0);
                Chz[(size_t)(r + 8) * ldc + (cc >> 1)] = __float2half_rn(a1);
            } else if (H16OUT) {
                *(__half2*)(Chz + (size_t)r * ldc + cc) =
                    __half2(__float2half_rn(v0), __float2half_rn(v1));
                *(__half2*)(Chz + (size_t)(r + 8) * ldc + cc) =
                    __half2(__float2half_rn(v2), __float2half_rn(v3));
            } else {
                if (ADDC) {
                    float2 a0 = *(const float2*)(ADz + (size_t)r * ldc + cc);
                    float2 a1 = *(const float2*)(ADz + (size_t)(r + 8) * ldc + cc);
                    v0 += a0.x; v1 += a0.y; v2 += a1.x; v3 += a1.y;
                }
                *(float2*)(Cfz + (size_t)r * ldc + cc)       = make_float2(v0, v1);
                *(float2*)(Cfz + (size_t)(r + 8) * ldc + cc) = make_float2(v2, v3);
            }
        }
    }
}

// ---------------- host launcher ----------------
extern "C" void kernel_launch(void* const* d_in, const int* in_sizes, int n_in,
                              void* d_out, int out_size)
{
    const float* hs    = (const float*)d_in[0];
    const float* resid = (const float*)d_in[1];
    const float* cosp  = (const float*)d_in[2];
    const float* sinp  = (const float*)d_in[3];
    const float* w_qkv = (const float*)d_in[4];
    const float* w_o   = (const float*)d_in[5];
    const float* w_gu  = (const float*)d_in[6];
    const float* w_dn  = (const float*)d_in[7];
    const float* ln1   = (const float*)d_in[8];
    const float* ln2   = (const float*)d_in[9];

    float* out     = (float*)d_out;
    float* mlp_out = out;
    float* res2    = out + (size_t)Tc * Hc;

    float *p_res1, *p_qkv, *p_scores;
    cudaGetSymbolAddress((void**)&p_res1,   g_res1);
    cudaGetSymbolAddress((void**)&p_qkv,    g_qkv);
    cudaGetSymbolAddress((void**)&p_scores, g_scores);
    __nv_bfloat16 *nh,*nl,*qh,*ql,*kh,*kl,*wqh,*wql;
    cudaGetSymbolAddress((void**)&nh,  g_n_hi);  cudaGetSymbolAddress((void**)&nl,  g_n_lo);
    cudaGetSymbolAddress((void**)&qh,  g_q_hi);  cudaGetSymbolAddress((void**)&ql,  g_q_lo);
    cudaGetSymbolAddress((void**)&kh,  g_k_hi);  cudaGetSymbolAddress((void**)&kl,  g_k_lo);
    cudaGetSymbolAddress((void**)&wqh, g_wqkv_hi); cudaGetSymbolAddress((void**)&wql, g_wqkv_lo);
    __half *ph,*vth,*ath,*n2h,*ach,*woh,*wgh,*wdh;
    cudaGetSymbolAddress((void**)&ph,  g_p_h);
    cudaGetSymbolAddress((void**)&vth, g_vt_h);
    cudaGetSymbolAddress((void**)&ath, g_at_h);
    cudaGetSymbolAddress((void**)&n2h, g_n2_h);
    cudaGetSymbolAddress((void**)&ach, g_ac_h);
    cudaGetSymbolAddress((void**)&woh, g_wo_h);
    cudaGetSymbolAddress((void**)&wgh, g_wgu_h);
    cudaGetSymbolAddress((void**)&wdh, g_wdn_h);

    cudaFuncSetAttribute(hmma_gemm_kernel<false>, cudaFuncAttributeMaxDynamicSharedMemorySize, gk::SMEM_SZ);
    cudaFuncSetAttribute(hmma_gemm_kernel<true>,  cudaFuncAttributeMaxDynamicSharedMemorySize, gk::SMEM_SZ);
    cudaFuncSetAttribute(h16_gemm_kernel<true, false,false,false>, cudaFuncAttributeMaxDynamicSharedMemorySize, hk::SMEM_SZ);
    cudaFuncSetAttribute(h16_gemm_kernel<false,false,false,false>, cudaFuncAttributeMaxDynamicSharedMemorySize, hk::SMEM_SZ);
    cudaFuncSetAttribute(h16_gemm_kernel<false,false,false,true >, cudaFuncAttributeMaxDynamicSharedMemorySize, hk::SMEM_SZ);
    cudaFuncSetAttribute(h16_gemm_kernel<false,true, true, false>, cudaFuncAttributeMaxDynamicSharedMemorySize, hk::SMEM_SZ);

    // weight prep
    transpose_convert_kernel<<<dim3(3*Hc/32, Hc/32), 256>>>(w_qkv, 3*Hc, wqh, wql, Hc);
    transpose_h16_kernel<<<dim3(Hc/32,   Hc/32), 256>>>(w_o,  0, 0, Hc,   woh, 0, Hc, 0);
    transpose_h16_kernel<<<dim3(2*Ic/32, Hc/32), 256>>>(w_gu, 0, 0, 2*Ic, wgh, 0, Hc, Ic); // interleaved
    transpose_h16_kernel<<<dim3(Hc/32,   Ic/32), 256>>>(w_dn, 0, 0, Hc,   wdh, 0, Ic, 0);

    // 1) res1 + RMSNorm -> bf16 planes
    add_rmsnorm_kernel<<<Tc, 256>>>(hs, resid, ln1, p_res1, nh, nl, nullptr);

    // 2) qkv = normed @ w_qkv (bf16 3-pass, fp32)
    hmma_gemm_kernel<false><<<dim3(3*Hc/128, Tc/256, 1), 256, gk::SMEM_SZ>>>(
        nh, nl, wqh, wql, p_qkv,
        Hc, Hc, Hc, 3*Hc, 0,0,0,0,0,0, 1.f);

    // 3) RoPE (bf16 q/k) + V transpose (fp16)
    rope_kernel<<<(Tc*2*NHc*HALFc)/256, 256>>>(p_qkv, cosp, sinp, qh, ql, kh, kl);
    transpose_h16_kernel<<<dim3(HDc/32, Sc/32, Bc*NHc), 256>>>(
        p_qkv + 2*Hc, (long long)Sc*3*Hc, HDc, 3*Hc, vth, (long long)HDc*Sc, Sc, 0);

    // 4) scores = scale * Q @ K^T (bf16 3-pass, causal)
    hmma_gemm_kernel<true><<<dim3(Sc/128, Sc/256, Bc*NHc), 256, gk::SMEM_SZ>>>(
        qh, ql, kh, kl, p_scores,
        HDc, Hc, Hc, Sc,
        (long long)Sc*Hc, HDc, (long long)Sc*Hc, HDc,
        (long long)NHc*Sc*Sc, (long long)Sc*Sc, SCALEc);

    // 5) softmax -> P fp16
    softmax_kernel<<<dim3(Sc, Bc*NHc), 256>>>(p_scores, ph);

    // 6) attn = P @ V (fp16 1-pass, K-limited, batched) -> ath fp16
    h16_gemm_kernel<false,true,true,false><<<dim3(1, Sc/128, Bc*NHc), 256, hk::SMEM_SZ>>>(
        ph, vth, nullptr, ath, nullptr,
        Sc, Sc, Sc, Hc,
        (long long)NHc*Sc*Sc, (long long)Sc*Sc,
        (long long)NHc*HDc*Sc, (long long)HDc*Sc,
        (long long)Sc*Hc, HDc);

    // 7) res2 = attn @ w_o + res1 (fp16 1-pass, into output)
    h16_gemm_kernel<true,false,false,false><<<dim3(Hc/128, Tc/128, 1), 256, hk::SMEM_SZ>>>(
        ath, woh, res2, nullptr, p_res1,
        Hc, Hc, Hc, Hc, 0,0,0,0,0,0);

    // 8) RMSNorm(res2) -> fp16 plane
    add_rmsnorm_kernel<<<Tc, 256>>>(res2, nullptr, ln2, nullptr, nullptr, nullptr, n2h);

    // 9) ac = silu(gate)*up fused (fp16 1-pass, interleaved weights)
    h16_gemm_kernel<false,false,false,true><<<dim3(2*Ic/128, Tc/128, 1), 256, hk::SMEM_SZ>>>(
        n2h, wgh, nullptr, ach, nullptr,
        Hc, Hc, Hc, Ic, 0,0,0,0,0,0);

    // 10) mlp_out = ac @ w_down (fp16 1-pass, into output)
    h16_gemm_kernel<false,false,false,false><<<dim3(Hc/128, Tc/128, 1), 256, hk::SMEM_SZ>>>(
        ach, wdh, mlp_out, nullptr, nullptr,
        Ic, Ic, Ic, Hc, 0,0,0,0,0,0);
}

// round 14
// speedup vs baseline: 5.6027x; 1.1846x over previous
#include <cuda_runtime.h>
#include <cuda_bf16.h>
#include <cuda_fp16.h>
#include <math.h>
#include <stdint.h>

namespace {
constexpr int Bc  = 2;
constexpr int Sc  = 2048;
constexpr int Hc  = 4096;
constexpr int NHc = 32;
constexpr int HDc = 128;
constexpr int Ic  = 11008;
constexpr int Tc  = Bc * Sc;
constexpr int HALFc = HDc / 2;
constexpr float EPSc = 1e-6f;
constexpr float SCALEc = 0.08838834764831843f;
}

// ---------------- device scratch ----------------
__device__ float g_res1  [(size_t)Tc * Hc];
__device__ float g_qkv   [(size_t)Tc * 3 * Hc];
__device__ float g_scores[(size_t)Bc * NHc * Sc * Sc];

__device__ __nv_bfloat16 g_q_hi [(size_t)Tc * Hc],  g_q_lo [(size_t)Tc * Hc];
__device__ __nv_bfloat16 g_k_hi [(size_t)Tc * Hc],  g_k_lo [(size_t)Tc * Hc];

// fp16 tensors
__device__ __half g_n_h1 [(size_t)Tc * Hc], g_n_h2 [(size_t)Tc * Hc];  // normed1 hi/lo
__device__ __half g_wqkv_h[(size_t)3 * Hc * Hc];
__device__ __half g_p_h  [(size_t)Bc * NHc * Sc * Sc];
__device__ __half g_vt_h [(size_t)Tc * Hc];
__device__ __half g_at_h [(size_t)Tc * Hc];
__device__ __half g_n2_h [(size_t)Tc * Hc];
__device__ __half g_ac_h [(size_t)Tc * Ic];
__device__ __half g_wo_h [(size_t)Hc * Hc];
__device__ __half g_wgu_h[(size_t)2 * Ic * Hc];          // interleaved gate/up rows
__device__ __half g_wdn_h[(size_t)Hc * Ic];

// ---------------- helpers ----------------
__device__ __forceinline__ uint32_t smem_u32(const void* p) {
    return (uint32_t)__cvta_generic_to_shared(p);
}
__device__ __forceinline__ void ldsm_x4(uint32_t (&r)[4], uint32_t addr) {
    asm volatile("ldmatrix.sync.aligned.m8n8.x4.shared.b16 {%0,%1,%2,%3}, [%4];"
                 : "=r"(r[0]), "=r"(r[1]), "=r"(r[2]), "=r"(r[3]) : "r"(addr));
}
__device__ __forceinline__ void mma_bf16(float (&d)[4], const uint32_t (&a)[4],
                                         uint32_t b0, uint32_t b1) {
    asm volatile("mma.sync.aligned.m16n8k16.row.col.f32.bf16.bf16.f32 "
        "{%0,%1,%2,%3}, {%4,%5,%6,%7}, {%8,%9}, {%0,%1,%2,%3};"
        : "+f"(d[0]), "+f"(d[1]), "+f"(d[2]), "+f"(d[3])
        : "r"(a[0]), "r"(a[1]), "r"(a[2]), "r"(a[3]), "r"(b0), "r"(b1));
}
__device__ __forceinline__ void mma_f16(float (&d)[4], const uint32_t (&a)[4],
                                        uint32_t b0, uint32_t b1) {
    asm volatile("mma.sync.aligned.m16n8k16.row.col.f32.f16.f16.f32 "
        "{%0,%1,%2,%3}, {%4,%5,%6,%7}, {%8,%9}, {%0,%1,%2,%3};"
        : "+f"(d[0]), "+f"(d[1]), "+f"(d[2]), "+f"(d[3])
        : "r"(a[0]), "r"(a[1]), "r"(a[2]), "r"(a[3]), "r"(b0), "r"(b1));
}
__device__ __forceinline__ void cp_async16(uint32_t dst, const void* src) {
    asm volatile("cp.async.cg.shared.global [%0], [%1], 16;" :: "r"(dst), "l"(src));
}
#define CP_COMMIT() asm volatile("cp.async.commit_group;" ::: "memory")
#define CP_WAIT(n)  asm volatile("cp.async.wait_group %0;" :: "n"(n) : "memory")
__device__ __forceinline__ void split2(float v, __nv_bfloat16& h, __nv_bfloat16& l) {
    h = __float2bfloat16(v);
    l = __float2bfloat16(v - __bfloat162float(h));
}
__device__ __forceinline__ void split2h(float v, __half& h, __half& l) {
    h = __float2half_rn(v);
    l = __float2half_rn(v - __half2float(h));
}

// ---------------- block reductions (256 thr) ----------------
__device__ __forceinline__ float block_reduce_sum_256(float v) {
    #pragma unroll
    for (int o = 16; o > 0; o >>= 1) v += __shfl_down_sync(0xffffffffu, v, o);
    __shared__ float red[8];
    int w = threadIdx.x >> 5, l = threadIdx.x & 31;
    if (l == 0) red[w] = v;
    __syncthreads();
    if (w == 0) {
        float x = (l < 8) ? red[l] : 0.f;
        #pragma unroll
        for (int o = 4; o > 0; o >>= 1) x += __shfl_down_sync(0xffu, x, o);
        if (l == 0) red[0] = x;
    }
    __syncthreads();
    float r = red[0];
    __syncthreads();
    return r;
}
__device__ __forceinline__ float block_reduce_max_256(float v) {
    #pragma unroll
    for (int o = 16; o > 0; o >>= 1) v = fmaxf(v, __shfl_down_sync(0xffffffffu, v, o));
    __shared__ float red[8];
    int w = threadIdx.x >> 5, l = threadIdx.x & 31;
    if (l == 0) red[w] = v;
    __syncthreads();
    if (w == 0) {
        float x = (l < 8) ? red[l] : -INFINITY;
        #pragma unroll
        for (int o = 4; o > 0; o >>= 1) x = fmaxf(x, __shfl_down_sync(0xffu, x, o));
        if (l == 0) red[0] = x;
    }
    __syncthreads();
    float r = red[0];
    __syncthreads();
    return r;
}

// ------- add + RMSNorm -> fp16 hi/lo duo OR fp16 single plane -------
__global__ __launch_bounds__(256) void add_rmsnorm_kernel(
    const float* __restrict__ a, const float* __restrict__ b,
    const float* __restrict__ w, float* __restrict__ sum_out,
    __half* __restrict__ ohi, __half* __restrict__ olo,
    __half* __restrict__ osingle)
{
    int row = blockIdx.x;
    const float4* a4 = (const float4*)(a + (size_t)row * Hc);
    const float4* b4 = b ? (const float4*)(b + (size_t)row * Hc) : nullptr;
    const float4* w4 = (const float4*)w;
    float4* s4 = sum_out ? (float4*)(sum_out + (size_t)row * Hc) : nullptr;

    float4 v[4];
    float ss = 0.f;
    #pragma unroll
    for (int it = 0; it < 4; it++) {
        int idx = threadIdx.x + it * 256;
        float4 va = a4[idx];
        if (b4) { float4 vb = b4[idx]; va.x += vb.x; va.y += vb.y; va.z += vb.z; va.w += vb.w; }
        v[it] = va;
        ss += va.x * va.x + va.y * va.y + va.z * va.z + va.w * va.w;
    }
    float tot = block_reduce_sum_256(ss);
    float scale = rsqrtf(tot / (float)Hc + EPSc);
    #pragma unroll
    for (int it = 0; it < 4; it++) {
        int idx = threadIdx.x + it * 256;
        if (s4) s4[idx] = v[it];
        float4 vw = w4[idx];
        float y0 = v[it].x * scale * vw.x, y1 = v[it].y * scale * vw.y;
        float y2 = v[it].z * scale * vw.z, y3 = v[it].w * scale * vw.w;
        if (osingle) {
            __half2* o2 = (__half2*)(osingle + (size_t)row * Hc);
            o2[idx*2]   = __half2(__float2half_rn(y0), __float2half_rn(y1));
            o2[idx*2+1] = __half2(__float2half_rn(y2), __float2half_rn(y3));
        } else {
            __half2* oh2 = (__half2*)(ohi + (size_t)row * Hc);
            __half2* ol2 = (__half2*)(olo + (size_t)row * Hc);
            __half h0,l0,h1,l1,h2,l2,h3,l3;
            split2h(y0,h0,l0); split2h(y1,h1,l1); split2h(y2,h2,l2); split2h(y3,h3,l3);
            oh2[idx*2]   = __half2(h0,h1);
            oh2[idx*2+1] = __half2(h2,h3);
            ol2[idx*2]   = __half2(l0,l1);
            ol2[idx*2+1] = __half2(l2,l3);
        }
    }
}

// ---------------- RoPE: fp32 qkv -> Q/K bf16 hi/lo ----------------
__global__ __launch_bounds__(256) void rope_kernel(
    const float* __restrict__ qkv, const float* __restrict__ cosp,
    const float* __restrict__ sinp,
    __nv_bfloat16* __restrict__ qhi, __nv_bfloat16* __restrict__ qlo,
    __nv_bfloat16* __restrict__ khi, __nv_bfloat16* __restrict__ klo)
{
    int idx = blockIdx.x * 256 + threadIdx.x;
    int d = idx & (HALFc - 1);
    int h = (idx >> 6) & (NHc - 1);
    int m = (idx >> 11) & 1;
    int t = idx >> 12;
    const float* p = qkv + (size_t)t * (3 * Hc) + m * Hc + h * HDc + d;
    float x1 = p[0], x2 = p[HALFc];
    float c = cosp[(size_t)t * HALFc + d];
    float s = sinp[(size_t)t * HALFc + d];
    float y1 = x1 * c - x2 * s;
    float y2 = x1 * s + x2 * c;
    __nv_bfloat16* dh = (m ? khi : qhi) + (size_t)t * Hc + h * HDc + d;
    __nv_bfloat16* dl = (m ? klo : qlo) + (size_t)t * Hc + h * HDc + d;
    __nv_bfloat16 h1, l1, h2, l2;
    split2(y1, h1, l1); split2(y2, h2, l2);
    dh[0] = h1; dh[HALFc] = h2;
    dl[0] = l1; dl[HALFc] = l2;
}

// ------- transpose fp32 [Y,X] -> fp16 [X,Y]; batched; optional interleave -------
__global__ __launch_bounds__(256) void transpose_h16_kernel(
    const float* __restrict__ in, long long inSb, long long inSh, int in_ld,
    __half* __restrict__ outp, long long outSz, int K, int interHalf)
{
    __shared__ float tile[32][33];
    int z = blockIdx.z, zb = z / NHc, zh = z % NHc;
    const float* inp = in + zb * inSb + zh * inSh;
    __half* op = outp + (long long)z * outSz;
    int tx = threadIdx.x & 31, ty = threadIdx.x >> 5;
    int gx = blockIdx.x * 32 + tx;
    #pragma unroll
    for (int i = 0; i < 4; i++) {
        int gy = blockIdx.y * 32 + ty + i * 8;
        tile[ty + i * 8][tx] = inp[(size_t)gy * in_ld + gx];
    }
    __syncthreads();
    int ox = blockIdx.y * 32 + tx;
    #pragma unroll
    for (int i = 0; i < 4; i++) {
        int oy = blockIdx.x * 32 + ty + i * 8;
        int oyr = interHalf ? ((oy < interHalf) ? 2 * oy : 2 * (oy - interHalf) + 1) : oy;
        op[(size_t)oyr * K + ox] = __float2half_rn(tile[tx][ty + i * 8]);
    }
}

// ------- causal softmax -> P fp16 (zero-fill to 128-aligned edge) -------
__global__ __launch_bounds__(256) void softmax_kernel(
    const float* __restrict__ scores, __half* __restrict__ ph)
{
    int i = blockIdx.x;
    int z = blockIdx.y;
    const float* row = scores + (size_t)z * Sc * Sc + (size_t)i * Sc;
    __half* pr = ph + (size_t)z * Sc * Sc + (size_t)i * Sc;
    int nvalid = i + 1;

    float vals[8];
    float mx = -INFINITY;
    #pragma unroll
    for (int it = 0; it < 8; it++) {
        int j = threadIdx.x + it * 256;
        float v = (j < nvalid) ? row[j] : -INFINITY;
        vals[it] = v;
        mx = fmaxf(mx, v);
    }
    float M = block_reduce_max_256(mx);
    float sum = 0.f;
    #pragma unroll
    for (int it = 0; it < 8; it++) {
        int j = threadIdx.x + it * 256;
        float e = (j < nvalid) ? __expf(vals[it] - M) : 0.f;
        vals[it] = e;
        sum += e;
    }
    float tot = block_reduce_sum_256(sum);
    float inv = 1.f / tot;
    int zero_end = ((i >> 7) + 1) << 7;
    #pragma unroll
    for (int it = 0; it < 8; it++) {
        int j = threadIdx.x + it * 256;
        if (j < zero_end) pr[j] = __float2half_rn(vals[it] * inv);
    }
}

// ==================================================================
// bf16 3-pass GEMM (QK^T only). BM=256, BN=128, BK=32, 256 thr,
// 8 warps 64x64, 2-stage cp.async.
// ==================================================================
namespace gk {
constexpr int BM = 256, BN = 128, BK = 32, SROW = 40;
constexpr int AOFF_L = BM * SROW * 2;
constexpr int BOFF_H = 2 * AOFF_L;
constexpr int BOFF_L = BOFF_H + BN * SROW * 2;
constexpr int STAGE  = BOFF_L + BN * SROW * 2;
constexpr int SMEM_SZ = 2 * STAGE;              // 122880
}

__global__ __launch_bounds__(256, 1) void qk_gemm_kernel(
    const __nv_bfloat16* __restrict__ Ahi, const __nv_bfloat16* __restrict__ Alo,
    const __nv_bfloat16* __restrict__ Bhi, const __nv_bfloat16* __restrict__ Blo,
    float* __restrict__ Cf,
    int K, int lda, int ldb, int ldc,
    long long sAh_, long long sBh_, long long sCh_,
    long long sAb, long long sBb, long long sCb, float alpha)
{
    using namespace gk;
    int rowBase = blockIdx.y * BM;
    int colBase = blockIdx.x * BN;
    if (colBase > rowBase + BM - 1) return;   // causal skip

    extern __shared__ char smraw[];
    uint32_t sbase = smem_u32(smraw);

    int tid = threadIdx.x;
    int wid = tid >> 5, lane = tid & 31;
    int wm = wid & 3, wn = wid >> 2;

    int z = blockIdx.z, zb = z / NHc, zh = z % NHc;
    const __nv_bfloat16* Ah = Ahi + zb * sAb + zh * sAh_;
    const __nv_bfloat16* Al = Alo + zb * sAb + zh * sAh_;
    const __nv_bfloat16* Bh = Bhi + zb * sBb + zh * sBh_;
    const __nv_bfloat16* Bl = Blo + zb * sBb + zh * sBh_;

    int nch = K / BK;

    float acc[4][8][4];
    #pragma unroll
    for (int a = 0; a < 4; a++)
        #pragma unroll
        for (int b = 0; b < 8; b++)
            #pragma unroll
            for (int c = 0; c < 4; c++) acc[a][b][c] = 0.f;

    int ar = tid >> 2, sg = (tid & 3) * 8;
    uint32_t soff = (uint32_t)(ar * SROW + sg) * 2;

    auto issue = [&](int c, int s) {
        int k0 = c * BK;
        uint32_t st = sbase + s * STAGE;
        #pragma unroll
        for (int it = 0; it < 4; it++) {
            int r = ar + it * 64;
            uint32_t o = soff + (uint32_t)(it * 64 * SROW) * 2;
            cp_async16(st + o,          Ah + (size_t)(rowBase + r) * lda + k0 + sg);
            cp_async16(st + AOFF_L + o, Al + (size_t)(rowBase + r) * lda + k0 + sg);
        }
        #pragma unroll
        for (int it = 0; it < 2; it++) {
            int r = ar + it * 64;
            uint32_t o = soff + (uint32_t)(it * 64 * SROW) * 2;
            cp_async16(st + BOFF_H + o, Bh + (size_t)(colBase + r) * ldb + k0 + sg);
            cp_async16(st + BOFF_L + o, Bl + (size_t)(colBase + r) * ldb + k0 + sg);
        }
    };

    int mat = lane >> 3, r8 = lane & 7;
    int a_row = (mat & 1) * 8 + r8, a_k = (mat >> 1) * 8;
    int b_n   = (mat >> 1) * 8 + r8, b_k = (mat & 1) * 8;

    issue(0, 0); CP_COMMIT();

    for (int c = 0; c < nch; ++c) {
        if (c + 1 < nch) { issue(c + 1, (c + 1) & 1); CP_COMMIT(); CP_WAIT(1); }
        else             { CP_WAIT(0); }
        __syncthreads();

        uint32_t st = sbase + (c & 1) * STAGE;
        #pragma unroll
        for (int ks = 0; ks < 2; ++ks) {
            uint32_t ah[4][4], al[4][4];
            #pragma unroll
            for (int mt = 0; mt < 4; ++mt) {
                uint32_t off = (uint32_t)((wm * 64 + mt * 16 + a_row) * SROW
                                          + ks * 16 + a_k) * 2;
                ldsm_x4(ah[mt], st + off);
                ldsm_x4(al[mt], st + AOFF_L + off);
            }
            #pragma unroll
            for (int nt = 0; nt < 4; ++nt) {
                uint32_t boff = (uint32_t)((wn * 64 + nt * 16 + b_n) * SROW
                                           + ks * 16 + b_k) * 2;
                uint32_t bh[4], bl[4];
                ldsm_x4(bh, st + BOFF_H + boff);
                ldsm_x4(bl, st + BOFF_L + boff);
                #pragma unroll
                for (int mt = 0; mt < 4; ++mt) {
                    #pragma unroll
                    for (int h2 = 0; h2 < 2; ++h2) {
                        mma_bf16(acc[mt][nt*2+h2], ah[mt], bh[2*h2], bh[2*h2+1]);
                        mma_bf16(acc[mt][nt*2+h2], ah[mt], bl[2*h2], bl[2*h2+1]);
                        mma_bf16(acc[mt][nt*2+h2], al[mt], bh[2*h2], bh[2*h2+1]);
                    }
                }
            }
        }
        __syncthreads();
    }

    float* Cfz = Cf + zb * sCb + zh * sCh_;
    #pragma unroll
    for (int mt = 0; mt < 4; ++mt) {
        int r = rowBase + wm * 64 + mt * 16 + (lane >> 2);
        #pragma unroll
        for (int j8 = 0; j8 < 8; ++j8) {
            int cc = colBase + wn * 64 + j8 * 8 + 2 * (lane & 3);
            *(float2*)(Cfz + (size_t)r * ldc + cc) =
                make_float2(acc[mt][j8][0] * alpha, acc[mt][j8][1] * alpha);
            *(float2*)(Cfz + (size_t)(r + 8) * ldc + cc) =
                make_float2(acc[mt][j8][2] * alpha, acc[mt][j8][3] * alpha);
        }
    }
}

// ==================================================================
// fp16 GEMM: C = (A [+A2]) @ B^T [+ADD]. BM=128, BN=128, BK=32,
// 256 thr, 8 warps 4x2 grid of 32x64 tiles, 3-stage cp.async.
// TWOA: A has hi/lo planes (2 mma passes, exact-activation path).
// KLIM / H16OUT / SILU as before. Batched via blockIdx.z strides.
// ==================================================================
namespace hk {
constexpr int BM = 128, BN = 128, BK = 32, SROW = 40;
constexpr int PL = BM * SROW * 2;               // 10240 per plane
}

template<bool ADDC, bool KLIM, bool H16OUT, bool SILU, bool TWOA>
__global__ __launch_bounds__(256, 2) void h16_gemm_kernel(
    const __half* __restrict__ A, const __half* __restrict__ A2,
    const __half* __restrict__ B,
    float* __restrict__ Cf, __half* __restrict__ Ch,
    const float* __restrict__ ADDp,
    int K, int lda, int ldb, int ldc,
    long long sAb, long long sAh_, long long sBb, long long sBh_,
    long long sCb, long long sCh_)
{
    using namespace hk;
    constexpr int BOFFB = TWOA ? 2 * PL : PL;
    constexpr int STAGE = BOFFB + PL;
    constexpr int NSTG  = 3;

    int rowBase = blockIdx.y * BM;
    int colBase = blockIdx.x * BN;

    extern __shared__ char smraw[];
    uint32_t sbase = smem_u32(smraw);

    int tid = threadIdx.x;
    int wid = tid >> 5, lane = tid & 31;
    int wm = wid & 3, wn = wid >> 2;

    int z = blockIdx.z, zb = z / NHc, zh = z % NHc;
    const __half* Az  = A  + zb * sAb + zh * sAh_;
    const __half* A2z = TWOA ? (A2 + zb * sAb + zh * sAh_) : nullptr;
    const __half* Bz  = B  + zb * sBb + zh * sBh_;

    int kEnd = KLIM ? min(K, rowBase + BM) : K;
    int nch  = kEnd / BK;

    float acc[2][8][4];
    #pragma unroll
    for (int a = 0; a < 2; a++)
        #pragma unroll
        for (int b = 0; b < 8; b++)
            #pragma unroll
            for (int c = 0; c < 4; c++) acc[a][b][c] = 0.f;

    int ar = tid >> 2, sg = (tid & 3) * 8;
    uint32_t soff = (uint32_t)(ar * SROW + sg) * 2;

    auto issue = [&](int c) {
        int k0 = c * BK;
        uint32_t st = sbase + (c % NSTG) * STAGE;
        #pragma unroll
        for (int it = 0; it < 2; it++) {
            int r = ar + it * 64;
            uint32_t o = soff + (uint32_t)(it * 64 * SROW) * 2;
            cp_async16(st + o,         Az + (size_t)(rowBase + r) * lda + k0 + sg);
            if (TWOA)
                cp_async16(st + PL + o, A2z + (size_t)(rowBase + r) * lda + k0 + sg);
            cp_async16(st + BOFFB + o, Bz + (size_t)(colBase + r) * ldb + k0 + sg);
        }
    };

    int mat = lane >> 3, r8 = lane & 7;
    int a_row = (mat & 1) * 8 + r8, a_k = (mat >> 1) * 8;
    int b_n   = (mat >> 1) * 8 + r8, b_k = (mat & 1) * 8;

    issue(0); CP_COMMIT();
    if (nch > 1) { issue(1); CP_COMMIT(); } else { CP_COMMIT(); }

    for (int c = 0; c < nch; ++c) {
        if (c + 2 < nch) issue(c + 2);
        CP_COMMIT();
        CP_WAIT(2);
        __syncthreads();

        uint32_t st = sbase + (c % NSTG) * STAGE;
        #pragma unroll
        for (int ks = 0; ks < 2; ++ks) {
            uint32_t af[2][4], af2[2][4];
            #pragma unroll
            for (int mt = 0; mt < 2; ++mt) {
                uint32_t off = (uint32_t)((wm * 32 + mt * 16 + a_row) * SROW
                                          + ks * 16 + a_k) * 2;
                ldsm_x4(af[mt], st + off);
                if (TWOA) ldsm_x4(af2[mt], st + PL + off);
            }
            #pragma unroll
            for (int nt = 0; nt < 4; ++nt) {
                uint32_t boff = (uint32_t)((wn * 64 + nt * 16 + b_n) * SROW
                                           + ks * 16 + b_k) * 2;
                uint32_t bf[4];
                ldsm_x4(bf, st + BOFFB + boff);
                #pragma unroll
                for (int mt = 0; mt < 2; ++mt) {
                    #pragma unroll
                    for (int h2 = 0; h2 < 2; ++h2) {
                        mma_f16(acc[mt][nt*2+h2], af[mt], bf[2*h2], bf[2*h2+1]);
                        if (TWOA)
                            mma_f16(acc[mt][nt*2+h2], af2[mt], bf[2*h2], bf[2*h2+1]);
                    }
                }
            }
        }
        __syncthreads();
    }

    float*  Cfz = Cf ? Cf + zb * sCb + zh * sCh_ : nullptr;
    __half* Chz = Ch ? Ch + zb * sCb + zh * sCh_ : nullptr;
    const float* ADz = ADDp ? ADDp + zb * sCb + zh * sCh_ : nullptr;

    #pragma unroll
    for (int mt = 0; mt < 2; ++mt) {
        int r = rowBase + wm * 32 + mt * 16 + (lane >> 2);
        #pragma unroll
        for (int j8 = 0; j8 < 8; ++j8) {
            int cc = colBase + wn * 64 + j8 * 8 + 2 * (lane & 3);
            float v0 = acc[mt][j8][0], v1 = acc[mt][j8][1];
            float v2 = acc[mt][j8][2], v3 = acc[mt][j8][3];
            if (SILU) {
                float a0 = v0 / (1.f + __expf(-v0)) * v1;
                float a1 = v2 / (1.f + __expf(-v2)) * v3;
                Chz[(size_t)r * ldc + (cc >> 1)]       = __float2half_rn(a0);
                Chz[(size_t)(r + 8) * ldc + (cc >> 1)] = __float2half_rn(a1);
            } else if (H16OUT) {
                *(__half2*)(Chz + (size_t)r * ldc + cc) =
                    __half2(__float2half_rn(v0), __float2half_rn(v1));
                *(__half2*)(Chz + (size_t)(r + 8) * ldc + cc) =
                    __half2(__float2half_rn(v2), __float2half_rn(v3));
            } else {
                if (ADDC) {
                    float2 a0 = *(const float2*)(ADz + (size_t)r * ldc + cc);
                    float2 a1 = *(const float2*)(ADz + (size_t)(r + 8) * ldc + cc);
                    v0 += a0.x; v1 += a0.y; v2 += a1.x; v3 += a1.y;
                }
                *(float2*)(Cfz + (size_t)r * ldc + cc)       = make_float2(v0, v1);
                *(float2*)(Cfz + (size_t)(r + 8) * ldc + cc) = make_float2(v2, v3);
            }
        }
    }
}

// ---------------- host launcher ----------------
extern "C" void kernel_launch(void* const* d_in, const int* in_sizes, int n_in,
                              void* d_out, int out_size)
{
    const float* hs    = (const float*)d_in[0];
    const float* resid = (const float*)d_in[1];
    const float* cosp  = (const float*)d_in[2];
    const float* sinp  = (const float*)d_in[3];
    const float* w_qkv = (const float*)d_in[4];
    const float* w_o   = (const float*)d_in[5];
    const float* w_gu  = (const float*)d_in[6];
    const float* w_dn  = (const float*)d_in[7];
    const float* ln1   = (const float*)d_in[8];
    const float* ln2   = (const float*)d_in[9];

    float* out     = (float*)d_out;
    float* mlp_out = out;
    float* res2    = out + (size_t)Tc * Hc;

    float *p_res1, *p_qkv, *p_scores;
    cudaGetSymbolAddress((void**)&p_res1,   g_res1);
    cudaGetSymbolAddress((void**)&p_qkv,    g_qkv);
    cudaGetSymbolAddress((void**)&p_scores, g_scores);
    __nv_bfloat16 *qh,*ql,*kh,*kl;
    cudaGetSymbolAddress((void**)&qh,  g_q_hi);  cudaGetSymbolAddress((void**)&ql,  g_q_lo);
    cudaGetSymbolAddress((void**)&kh,  g_k_hi);  cudaGetSymbolAddress((void**)&kl,  g_k_lo);
    __half *nh1,*nh2,*wqh,*ph,*vth,*ath,*n2h,*ach,*woh,*wgh,*wdh;
    cudaGetSymbolAddress((void**)&nh1, g_n_h1);
    cudaGetSymbolAddress((void**)&nh2, g_n_h2);
    cudaGetSymbolAddress((void**)&wqh, g_wqkv_h);
    cudaGetSymbolAddress((void**)&ph,  g_p_h);
    cudaGetSymbolAddress((void**)&vth, g_vt_h);
    cudaGetSymbolAddress((void**)&ath, g_at_h);
    cudaGetSymbolAddress((void**)&n2h, g_n2_h);
    cudaGetSymbolAddress((void**)&ach, g_ac_h);
    cudaGetSymbolAddress((void**)&woh, g_wo_h);
    cudaGetSymbolAddress((void**)&wgh, g_wgu_h);
    cudaGetSymbolAddress((void**)&wdh, g_wdn_h);

    constexpr int SM1 = 3 * (2 * hk::PL);   // 61440 (1-plane A)
    constexpr int SM2 = 3 * (3 * hk::PL);   // 92160 (2-plane A)
    cudaFuncSetAttribute(qk_gemm_kernel, cudaFuncAttributeMaxDynamicSharedMemorySize, gk::SMEM_SZ);
    cudaFuncSetAttribute(h16_gemm_kernel<true, false,false,false,false>, cudaFuncAttributeMaxDynamicSharedMemorySize, SM1);
    cudaFuncSetAttribute(h16_gemm_kernel<false,false,false,false,false>, cudaFuncAttributeMaxDynamicSharedMemorySize, SM1);
    cudaFuncSetAttribute(h16_gemm_kernel<false,false,false,true, false>, cudaFuncAttributeMaxDynamicSharedMemorySize, SM1);
    cudaFuncSetAttribute(h16_gemm_kernel<false,true, true, false,false>, cudaFuncAttributeMaxDynamicSharedMemorySize, SM1);
    cudaFuncSetAttribute(h16_gemm_kernel<false,false,false,false,true >, cudaFuncAttributeMaxDynamicSharedMemorySize, SM2);

    // weight prep (all fp16 single plane; wgu interleaved)
    transpose_h16_kernel<<<dim3(3*Hc/32, Hc/32), 256>>>(w_qkv, 0, 0, 3*Hc, wqh, 0, Hc, 0);
    transpose_h16_kernel<<<dim3(Hc/32,   Hc/32), 256>>>(w_o,  0, 0, Hc,   woh, 0, Hc, 0);
    transpose_h16_kernel<<<dim3(2*Ic/32, Hc/32), 256>>>(w_gu, 0, 0, 2*Ic, wgh, 0, Hc, Ic);
    transpose_h16_kernel<<<dim3(Hc/32,   Ic/32), 256>>>(w_dn, 0, 0, Hc,   wdh, 0, Ic, 0);

    // 1) res1 + RMSNorm -> fp16 hi/lo duo
    add_rmsnorm_kernel<<<Tc, 256>>>(hs, resid, ln1, p_res1, nh1, nh2, nullptr);

    // 2) qkv = normed @ w_qkv (fp16 2-pass TWOA, fp32 out)
    h16_gemm_kernel<false,false,false,false,true><<<dim3(3*Hc/128, Tc/128, 1), 256, SM2>>>(
        nh1, nh2, wqh, p_qkv, nullptr, nullptr,
        Hc, Hc, Hc, 3*Hc, 0,0,0,0,0,0);

    // 3) RoPE (bf16 q/k) + V transpose (fp16)
    rope_kernel<<<(Tc*2*NHc*HALFc)/256, 256>>>(p_qkv, cosp, sinp, qh, ql, kh, kl);
    transpose_h16_kernel<<<dim3(HDc/32, Sc/32, Bc*NHc), 256>>>(
        p_qkv + 2*Hc, (long long)Sc*3*Hc, HDc, 3*Hc, vth, (long long)HDc*Sc, Sc, 0);

    // 4) scores = scale * Q @ K^T (bf16 3-pass, causal)
    qk_gemm_kernel<<<dim3(Sc/128, Sc/256, Bc*NHc), 256, gk::SMEM_SZ>>>(
        qh, ql, kh, kl, p_scores,
        HDc, Hc, Hc, Sc,
        HDc, HDc, (long long)Sc*Sc,
        (long long)Sc*Hc, (long long)Sc*Hc, (long long)NHc*Sc*Sc, SCALEc);

    // 5) softmax -> P fp16
    softmax_kernel<<<dim3(Sc, Bc*NHc), 256>>>(p_scores, ph);

    // 6) attn = P @ V (fp16 1-pass, K-limited, batched) -> ath fp16
    h16_gemm_kernel<false,true,true,false,false><<<dim3(1, Sc/128, Bc*NHc), 256, SM1>>>(
        ph, nullptr, vth, nullptr, ath, nullptr,
        Sc, Sc, Sc, Hc,
        (long long)NHc*Sc*Sc, (long long)Sc*Sc,
        (long long)NHc*HDc*Sc, (long long)HDc*Sc,
        (long long)Sc*Hc, HDc);

    // 7) res2 = attn @ w_o + res1 (fp16 1-pass, into output)
    h16_gemm_kernel<true,false,false,false,false><<<dim3(Hc/128, Tc/128, 1), 256, SM1>>>(
        ath, nullptr, woh, res2, nullptr, p_res1,
        Hc, Hc, Hc, Hc, 0,0,0,0,0,0);

    // 8) RMSNorm(res2) -> fp16 single plane
    add_rmsnorm_kernel<<<Tc, 256>>>(res2, nullptr, ln2, nullptr, nullptr, nullptr, n2h);

    // 9) ac = silu(gate)*up fused (fp16 1-pass, interleaved weights)
    h16_gemm_kernel<false,false,false,true,false><<<dim3(2*Ic/128, Tc/128, 1), 256, SM1>>>(
        n2h, nullptr, wgh, nullptr, ach, nullptr,
        Hc, Hc, Hc, Ic, 0,0,0,0,0,0);

    // 10) mlp_out = ac @ w_down (fp16 1-pass, into output)
    h16_gemm_kernel<false,false,false,false,false><<<dim3(Hc/128, Tc/128, 1), 256, SM1>>>(
        ach, nullptr, wdh, mlp_out, nullptr, nullptr,
        Ic, Ic, Ic, Hc, 0,0,0,0,0,0);
}

// round 15
// speedup vs baseline: 5.9073x; 1.0544x over previous
#include <cuda_runtime.h>
#include <cuda_bf16.h>
#include <cuda_fp16.h>
#include <math.h>
#include <stdint.h>

namespace {
constexpr int Bc  = 2;
constexpr int Sc  = 2048;
constexpr int Hc  = 4096;
constexpr int NHc = 32;
constexpr int HDc = 128;
constexpr int Ic  = 11008;
constexpr int Tc  = Bc * Sc;
constexpr int HALFc = HDc / 2;
constexpr float EPSc = 1e-6f;
constexpr float SCALEc = 0.08838834764831843f;
}

// ---------------- device scratch ----------------
__device__ float g_res1[(size_t)Tc * Hc];
__device__ float g_qkv [(size_t)Tc * 3 * Hc];

__device__ __nv_bfloat16 g_q_hi[(size_t)Tc * Hc], g_q_lo[(size_t)Tc * Hc];
__device__ __nv_bfloat16 g_k_hi[(size_t)Tc * Hc], g_k_lo[(size_t)Tc * Hc];

__device__ __half g_n_h1 [(size_t)Tc * Hc], g_n_h2 [(size_t)Tc * Hc];
__device__ __half g_wqkv_h[(size_t)3 * Hc * Hc];
__device__ __half g_vt_h [(size_t)Tc * Hc];
__device__ __half g_at_h [(size_t)Tc * Hc];
__device__ __half g_n2_h [(size_t)Tc * Hc];
__device__ __half g_ac_h [(size_t)Tc * Ic];
__device__ __half g_wo_h [(size_t)Hc * Hc];
__device__ __half g_wgu_h[(size_t)2 * Ic * Hc];
__device__ __half g_wdn_h[(size_t)Hc * Ic];

// ---------------- helpers ----------------
__device__ __forceinline__ uint32_t smem_u32(const void* p) {
    return (uint32_t)__cvta_generic_to_shared(p);
}
__device__ __forceinline__ void ldsm_x4(uint32_t (&r)[4], uint32_t addr) {
    asm volatile("ldmatrix.sync.aligned.m8n8.x4.shared.b16 {%0,%1,%2,%3}, [%4];"
                 : "=r"(r[0]), "=r"(r[1]), "=r"(r[2]), "=r"(r[3]) : "r"(addr));
}
__device__ __forceinline__ void mma_bf16(float (&d)[4], const uint32_t (&a)[4],
                                         uint32_t b0, uint32_t b1) {
    asm volatile("mma.sync.aligned.m16n8k16.row.col.f32.bf16.bf16.f32 "
        "{%0,%1,%2,%3}, {%4,%5,%6,%7}, {%8,%9}, {%0,%1,%2,%3};"
        : "+f"(d[0]), "+f"(d[1]), "+f"(d[2]), "+f"(d[3])
        : "r"(a[0]), "r"(a[1]), "r"(a[2]), "r"(a[3]), "r"(b0), "r"(b1));
}
__device__ __forceinline__ void mma_f16(float (&d)[4], const uint32_t (&a)[4],
                                        uint32_t b0, uint32_t b1) {
    asm volatile("mma.sync.aligned.m16n8k16.row.col.f32.f16.f16.f32 "
        "{%0,%1,%2,%3}, {%4,%5,%6,%7}, {%8,%9}, {%0,%1,%2,%3};"
        : "+f"(d[0]), "+f"(d[1]), "+f"(d[2]), "+f"(d[3])
        : "r"(a[0]), "r"(a[1]), "r"(a[2]), "r"(a[3]), "r"(b0), "r"(b1));
}
__device__ __forceinline__ void cp_async16(uint32_t dst, const void* src) {
    asm volatile("cp.async.cg.shared.global [%0], [%1], 16;" :: "r"(dst), "l"(src));
}
#define CP_COMMIT() asm volatile("cp.async.commit_group;" ::: "memory")
#define CP_WAIT(n)  asm volatile("cp.async.wait_group %0;" :: "n"(n) : "memory")
__device__ __forceinline__ void split2(float v, __nv_bfloat16& h, __nv_bfloat16& l) {
    h = __float2bfloat16(v);
    l = __float2bfloat16(v - __bfloat162float(h));
}
__device__ __forceinline__ void split2h(float v, __half& h, __half& l) {
    h = __float2half_rn(v);
    l = __float2half_rn(v - __half2float(h));
}

// ---------------- block reductions (256 thr) ----------------
__device__ __forceinline__ float block_reduce_sum_256(float v) {
    #pragma unroll
    for (int o = 16; o > 0; o >>= 1) v += __shfl_down_sync(0xffffffffu, v, o);
    __shared__ float red[8];
    int w = threadIdx.x >> 5, l = threadIdx.x & 31;
    if (l == 0) red[w] = v;
    __syncthreads();
    if (w == 0) {
        float x = (l < 8) ? red[l] : 0.f;
        #pragma unroll
        for (int o = 4; o > 0; o >>= 1) x += __shfl_down_sync(0xffu, x, o);
        if (l == 0) red[0] = x;
    }
    __syncthreads();
    float r = red[0];
    __syncthreads();
    return r;
}

// ------- add + RMSNorm -> fp16 hi/lo duo OR fp16 single plane -------
__global__ __launch_bounds__(256) void add_rmsnorm_kernel(
    const float* __restrict__ a, const float* __restrict__ b,
    const float* __restrict__ w, float* __restrict__ sum_out,
    __half* __restrict__ ohi, __half* __restrict__ olo,
    __half* __restrict__ osingle)
{
    int row = blockIdx.x;
    const float4* a4 = (const float4*)(a + (size_t)row * Hc);
    const float4* b4 = b ? (const float4*)(b + (size_t)row * Hc) : nullptr;
    const float4* w4 = (const float4*)w;
    float4* s4 = sum_out ? (float4*)(sum_out + (size_t)row * Hc) : nullptr;

    float4 v[4];
    float ss = 0.f;
    #pragma unroll
    for (int it = 0; it < 4; it++) {
        int idx = threadIdx.x + it * 256;
        float4 va = a4[idx];
        if (b4) { float4 vb = b4[idx]; va.x += vb.x; va.y += vb.y; va.z += vb.z; va.w += vb.w; }
        v[it] = va;
        ss += va.x * va.x + va.y * va.y + va.z * va.z + va.w * va.w;
    }
    float tot = block_reduce_sum_256(ss);
    float scale = rsqrtf(tot / (float)Hc + EPSc);
    #pragma unroll
    for (int it = 0; it < 4; it++) {
        int idx = threadIdx.x + it * 256;
        if (s4) s4[idx] = v[it];
        float4 vw = w4[idx];
        float y0 = v[it].x * scale * vw.x, y1 = v[it].y * scale * vw.y;
        float y2 = v[it].z * scale * vw.z, y3 = v[it].w * scale * vw.w;
        if (osingle) {
            __half2* o2 = (__half2*)(osingle + (size_t)row * Hc);
            o2[idx*2]   = __half2(__float2half_rn(y0), __float2half_rn(y1));
            o2[idx*2+1] = __half2(__float2half_rn(y2), __float2half_rn(y3));
        } else {
            __half2* oh2 = (__half2*)(ohi + (size_t)row * Hc);
            __half2* ol2 = (__half2*)(olo + (size_t)row * Hc);
            __half h0,l0,h1,l1,h2,l2,h3,l3;
            split2h(y0,h0,l0); split2h(y1,h1,l1); split2h(y2,h2,l2); split2h(y3,h3,l3);
            oh2[idx*2]   = __half2(h0,h1);
            oh2[idx*2+1] = __half2(h2,h3);
            ol2[idx*2]   = __half2(l0,l1);
            ol2[idx*2+1] = __half2(l2,l3);
        }
    }
}

// ------- RoPE: fp32 qkv -> Q/K bf16 hi/lo (SCALE folded into Q) -------
__global__ __launch_bounds__(256) void rope_kernel(
    const float* __restrict__ qkv, const float* __restrict__ cosp,
    const float* __restrict__ sinp,
    __nv_bfloat16* __restrict__ qhi, __nv_bfloat16* __restrict__ qlo,
    __nv_bfloat16* __restrict__ khi, __nv_bfloat16* __restrict__ klo)
{
    int idx = blockIdx.x * 256 + threadIdx.x;
    int d = idx & (HALFc - 1);
    int h = (idx >> 6) & (NHc - 1);
    int m = (idx >> 11) & 1;
    int t = idx >> 12;
    const float* p = qkv + (size_t)t * (3 * Hc) + m * Hc + h * HDc + d;
    float x1 = p[0], x2 = p[HALFc];
    float c = cosp[(size_t)t * HALFc + d];
    float s = sinp[(size_t)t * HALFc + d];
    float sc = m ? 1.f : SCALEc;
    float y1 = (x1 * c - x2 * s) * sc;
    float y2 = (x1 * s + x2 * c) * sc;
    __nv_bfloat16* dh = (m ? khi : qhi) + (size_t)t * Hc + h * HDc + d;
    __nv_bfloat16* dl = (m ? klo : qlo) + (size_t)t * Hc + h * HDc + d;
    __nv_bfloat16 h1, l1, h2, l2;
    split2(y1, h1, l1); split2(y2, h2, l2);
    dh[0] = h1; dh[HALFc] = h2;
    dl[0] = l1; dl[HALFc] = l2;
}

// ------- transpose fp32 [Y,X] -> fp16 [X,Y]; batched; optional interleave -------
__global__ __launch_bounds__(256) void transpose_h16_kernel(
    const float* __restrict__ in, long long inSb, long long inSh, int in_ld,
    __half* __restrict__ outp, long long outSz, int K, int interHalf)
{
    __shared__ float tile[32][33];
    int z = blockIdx.z, zb = z / NHc, zh = z % NHc;
    const float* inp = in + zb * inSb + zh * inSh;
    __half* op = outp + (long long)z * outSz;
    int tx = threadIdx.x & 31, ty = threadIdx.x >> 5;
    int gx = blockIdx.x * 32 + tx;
    #pragma unroll
    for (int i = 0; i < 4; i++) {
        int gy = blockIdx.y * 32 + ty + i * 8;
        tile[ty + i * 8][tx] = inp[(size_t)gy * in_ld + gx];
    }
    __syncthreads();
    int ox = blockIdx.y * 32 + tx;
    #pragma unroll
    for (int i = 0; i < 4; i++) {
        int oy = blockIdx.x * 32 + ty + i * 8;
        int oyr = interHalf ? ((oy < interHalf) ? 2 * oy : 2 * (oy - interHalf) + 1) : oy;
        op[(size_t)oyr * K + ox] = __float2half_rn(tile[tx][ty + i * 8]);
    }
}

// ==================================================================
// Fused flash attention: per (z, 128-row block) stream 128-col K/V
// blocks. QK = bf16 3-pass, online softmax fp32, PV = fp16 1-pass.
// 8 warps x 16 rows. smem: Qhi,Qlo,Khi,Klo,V tiles (128x136 halves).
// ==================================================================
namespace fa {
constexpr int SROW = 136;                  // halves per row (pad 8)
constexpr int TILE = 128 * SROW * 2;       // 34816 B
constexpr int QH_OFF = 0, QL_OFF = TILE, KH_OFF = 2*TILE, KL_OFF = 3*TILE, V_OFF = 4*TILE;
constexpr int SMEM_SZ = 5 * TILE;          // 174080
}

__global__ __launch_bounds__(256, 1) void flash_attn_kernel(
    const __nv_bfloat16* __restrict__ Qhi, const __nv_bfloat16* __restrict__ Qlo,
    const __nv_bfloat16* __restrict__ Khi, const __nv_bfloat16* __restrict__ Klo,
    const __half* __restrict__ Vt, __half* __restrict__ Out)
{
    using namespace fa;
    extern __shared__ char smraw[];
    uint32_t sbase = smem_u32(smraw);

    int tid = threadIdx.x;
    int wid = tid >> 5, lane = tid & 31;
    int z = blockIdx.z, zb = z / NHc, zh = z % NHc;
    int rowBase = blockIdx.y * 128;
    int nb = rowBase / 128 + 1;

    // global bases
    const __nv_bfloat16* Qh = Qhi + (size_t)(zb * Sc) * Hc + zh * HDc;
    const __nv_bfloat16* Ql = Qlo + (size_t)(zb * Sc) * Hc + zh * HDc;
    const __nv_bfloat16* Kh = Khi + (size_t)(zb * Sc) * Hc + zh * HDc;
    const __nv_bfloat16* Kl = Klo + (size_t)(zb * Sc) * Hc + zh * HDc;
    const __half* V = Vt + (size_t)z * HDc * Sc;

    // tile loader: 128 rows x 128 halves, row stride gstride (halves)
    int lr = tid >> 4;              // +16 per it
    int lc = (tid & 15) * 8;
    uint32_t lso = (uint32_t)(lr * SROW + lc) * 2;
    auto load16 = [&](uint32_t dst, const void* src) { cp_async16(dst, src); };

    // ldmatrix lane addressing (verified mapping)
    int mat = lane >> 3, r8 = lane & 7;
    int a_row = (mat & 1) * 8 + r8, a_k = (mat >> 1) * 8;
    int b_n   = (mat >> 1) * 8 + r8, b_k = (mat & 1) * 8;
    int gid = lane >> 2;            // row group 0..7
    int e2  = 2 * (lane & 3);       // col pair base

    float o[16][4];
    #pragma unroll
    for (int j = 0; j < 16; j++)
        #pragma unroll
        for (int c = 0; c < 4; c++) o[j][c] = 0.f;
    float m0 = -INFINITY, m1 = -INFINITY, l0 = 0.f, l1 = 0.f;

    // load Q (once)
    #pragma unroll
    for (int it = 0; it < 8; it++) {
        int r = lr + it * 16;
        uint32_t so = lso + (uint32_t)(it * 16 * SROW) * 2;
        load16(sbase + QH_OFF + so, Qh + (size_t)(rowBase + r) * Hc + lc);
        load16(sbase + QL_OFF + so, Ql + (size_t)(rowBase + r) * Hc + lc);
    }

    for (int b = 0; b < nb; b++) {
        int sBase = b * 128;
        #pragma unroll
        for (int it = 0; it < 8; it++) {
            int r = lr + it * 16;
            uint32_t so = lso + (uint32_t)(it * 16 * SROW) * 2;
            load16(sbase + KH_OFF + so, Kh + (size_t)(sBase + r) * Hc + lc);
            load16(sbase + KL_OFF + so, Kl + (size_t)(sBase + r) * Hc + lc);
            load16(sbase + V_OFF  + so, V + (size_t)r * Sc + sBase + lc);
        }
        CP_COMMIT();
        CP_WAIT(0);
        __syncthreads();

        // S = Q @ K^T  (bf16 3-pass)
        float s[16][4];
        #pragma unroll
        for (int j = 0; j < 16; j++)
            #pragma unroll
            for (int c = 0; c < 4; c++) s[j][c] = 0.f;

        #pragma unroll
        for (int ks = 0; ks < 8; ks++) {
            uint32_t qoff = (uint32_t)((wid * 16 + a_row) * SROW + ks * 16 + a_k) * 2;
            uint32_t ah[4], al[4];
            ldsm_x4(ah, sbase + QH_OFF + qoff);
            ldsm_x4(al, sbase + QL_OFF + qoff);
            #pragma unroll
            for (int nt = 0; nt < 8; nt++) {
                uint32_t koff = (uint32_t)((nt * 16 + b_n) * SROW + ks * 16 + b_k) * 2;
                uint32_t bh[4], bl[4];
                ldsm_x4(bh, sbase + KH_OFF + koff);
                ldsm_x4(bl, sbase + KL_OFF + koff);
                #pragma unroll
                for (int h2 = 0; h2 < 2; h2++) {
                    mma_bf16(s[nt*2+h2], ah, bh[2*h2], bh[2*h2+1]);
                    mma_bf16(s[nt*2+h2], ah, bl[2*h2], bl[2*h2+1]);
                    mma_bf16(s[nt*2+h2], al, bh[2*h2], bh[2*h2+1]);
                }
            }
        }

        // causal mask (diagonal block only)
        if (b == nb - 1) {
            int row0 = rowBase + wid * 16 + gid;
            #pragma unroll
            for (int j = 0; j < 16; j++) {
                int col = sBase + j * 8 + e2;
                if (col     > row0)     s[j][0] = -INFINITY;
                if (col + 1 > row0)     s[j][1] = -INFINITY;
                if (col     > row0 + 8) s[j][2] = -INFINITY;
                if (col + 1 > row0 + 8) s[j][3] = -INFINITY;
            }
        }

        // row max (within 4-lane group)
        float bm0 = -INFINITY, bm1 = -INFINITY;
        #pragma unroll
        for (int j = 0; j < 16; j++) {
            bm0 = fmaxf(bm0, fmaxf(s[j][0], s[j][1]));
            bm1 = fmaxf(bm1, fmaxf(s[j][2], s[j][3]));
        }
        #pragma unroll
        for (int off = 1; off <= 2; off <<= 1) {
            bm0 = fmaxf(bm0, __shfl_xor_sync(0xffffffffu, bm0, off));
            bm1 = fmaxf(bm1, __shfl_xor_sync(0xffffffffu, bm1, off));
        }
        float mn0 = fmaxf(m0, bm0), mn1 = fmaxf(m1, bm1);
        float cr0 = __expf(m0 - mn0), cr1 = __expf(m1 - mn1);
        m0 = mn0; m1 = mn1;

        // p = exp(s - m); row sums
        float rs0 = 0.f, rs1 = 0.f;
        #pragma unroll
        for (int j = 0; j < 16; j++) {
            s[j][0] = __expf(s[j][0] - mn0);
            s[j][1] = __expf(s[j][1] - mn0);
            s[j][2] = __expf(s[j][2] - mn1);
            s[j][3] = __expf(s[j][3] - mn1);
            rs0 += s[j][0] + s[j][1];
            rs1 += s[j][2] + s[j][3];
        }
        #pragma unroll
        for (int off = 1; off <= 2; off <<= 1) {
            rs0 += __shfl_xor_sync(0xffffffffu, rs0, off);
            rs1 += __shfl_xor_sync(0xffffffffu, rs1, off);
        }
        l0 = l0 * cr0 + rs0;
        l1 = l1 * cr1 + rs1;
        #pragma unroll
        for (int j = 0; j < 16; j++) {
            o[j][0] *= cr0; o[j][1] *= cr0;
            o[j][2] *= cr1; o[j][3] *= cr1;
        }

        // PV: A frags from p (fp16), B = V smem tile
        #pragma unroll
        for (int kk = 0; kk < 8; kk++) {
            uint32_t a[4];
            a[0] = __half2_raw(__half2(__float2half_rn(s[2*kk][0]),   __float2half_rn(s[2*kk][1]))).x |
                   ((uint32_t)__half2_raw(__half2(__float2half_rn(s[2*kk][0]), __float2half_rn(s[2*kk][1]))).y << 16);
            // build via memcpy-safe path:
            __half2 h0 = __half2(__float2half_rn(s[2*kk][0]),   __float2half_rn(s[2*kk][1]));
            __half2 h1 = __half2(__float2half_rn(s[2*kk][2]),   __float2half_rn(s[2*kk][3]));
            __half2 h2 = __half2(__float2half_rn(s[2*kk+1][0]), __float2half_rn(s[2*kk+1][1]));
            __half2 h3 = __half2(__float2half_rn(s[2*kk+1][2]), __float2half_rn(s[2*kk+1][3]));
            a[0] = *(uint32_t*)&h0;
            a[1] = *(uint32_t*)&h1;
            a[2] = *(uint32_t*)&h2;
            a[3] = *(uint32_t*)&h3;
            #pragma unroll
            for (int nt = 0; nt < 8; nt++) {
                uint32_t voff = (uint32_t)((nt * 16 + b_n) * SROW + kk * 16 + b_k) * 2;
                uint32_t bv[4];
                ldsm_x4(bv, sbase + V_OFF + voff);
                #pragma unroll
                for (int h2i = 0; h2i < 2; h2i++)
                    mma_f16(o[nt*2+h2i], a, bv[2*h2i], bv[2*h2i+1]);
            }
        }
        __syncthreads();
    }

    // normalize + write fp16 [T, H]
    float i0 = 1.f / l0, i1 = 1.f / l1;
    __half* ob = Out + (size_t)(zb * Sc + rowBase + wid * 16 + gid) * Hc + zh * HDc;
    #pragma unroll
    for (int j = 0; j < 16; j++) {
        int col = j * 8 + e2;
        *(__half2*)(ob + col) =
            __half2(__float2half_rn(o[j][0] * i0), __float2half_rn(o[j][1] * i0));
        *(__half2*)(ob + 8 * Hc + col) =
            __half2(__float2half_rn(o[j][2] * i1), __float2half_rn(o[j][3] * i1));
    }
}

// ==================================================================
// fp16 GEMM: C = (A [+A2]) @ B^T [+ADD]. BM=128, BN=128, BK=32,
// 256 thr, 8 warps 4x2 grid of 32x64 tiles, 3-stage cp.async.
// ==================================================================
namespace hk {
constexpr int BM = 128, BN = 128, BK = 32, SROW = 40;
constexpr int PL = BM * SROW * 2;
}

template<bool ADDC, bool H16OUT, bool SILU, bool TWOA>
__global__ __launch_bounds__(256, 2) void h16_gemm_kernel(
    const __half* __restrict__ A, const __half* __restrict__ A2,
    const __half* __restrict__ B,
    float* __restrict__ Cf, __half* __restrict__ Ch,
    const float* __restrict__ ADDp,
    int K, int lda, int ldb, int ldc)
{
    using namespace hk;
    constexpr int BOFFB = TWOA ? 2 * PL : PL;
    constexpr int STAGE = BOFFB + PL;
    constexpr int NSTG  = 3;

    int rowBase = blockIdx.y * BM;
    int colBase = blockIdx.x * BN;

    extern __shared__ char smraw[];
    uint32_t sbase = smem_u32(smraw);

    int tid = threadIdx.x;
    int wid = tid >> 5, lane = tid & 31;
    int wm = wid & 3, wn = wid >> 2;

    int nch = K / BK;

    float acc[2][8][4];
    #pragma unroll
    for (int a = 0; a < 2; a++)
        #pragma unroll
        for (int b = 0; b < 8; b++)
            #pragma unroll
            for (int c = 0; c < 4; c++) acc[a][b][c] = 0.f;

    int ar = tid >> 2, sg = (tid & 3) * 8;
    uint32_t soff = (uint32_t)(ar * SROW + sg) * 2;

    auto issue = [&](int c) {
        int k0 = c * BK;
        uint32_t st = sbase + (c % NSTG) * STAGE;
        #pragma unroll
        for (int it = 0; it < 2; it++) {
            int r = ar + it * 64;
            uint32_t o = soff + (uint32_t)(it * 64 * SROW) * 2;
            cp_async16(st + o,         A + (size_t)(rowBase + r) * lda + k0 + sg);
            if (TWOA)
                cp_async16(st + PL + o, A2 + (size_t)(rowBase + r) * lda + k0 + sg);
            cp_async16(st + BOFFB + o, B + (size_t)(colBase + r) * ldb + k0 + sg);
        }
    };

    int mat = lane >> 3, r8 = lane & 7;
    int a_row = (mat & 1) * 8 + r8, a_k = (mat >> 1) * 8;
    int b_n   = (mat >> 1) * 8 + r8, b_k = (mat & 1) * 8;

    issue(0); CP_COMMIT();
    if (nch > 1) { issue(1); CP_COMMIT(); } else { CP_COMMIT(); }

    for (int c = 0; c < nch; ++c) {
        if (c + 2 < nch) issue(c + 2);
        CP_COMMIT();
        CP_WAIT(2);
        __syncthreads();

        uint32_t st = sbase + (c % NSTG) * STAGE;
        #pragma unroll
        for (int ks = 0; ks < 2; ++ks) {
            uint32_t af[2][4], af2[2][4];
            #pragma unroll
            for (int mt = 0; mt < 2; ++mt) {
                uint32_t off = (uint32_t)((wm * 32 + mt * 16 + a_row) * SROW
                                          + ks * 16 + a_k) * 2;
                ldsm_x4(af[mt], st + off);
                if (TWOA) ldsm_x4(af2[mt], st + PL + off);
            }
            #pragma unroll
            for (int nt = 0; nt < 4; ++nt) {
                uint32_t boff = (uint32_t)((wn * 64 + nt * 16 + b_n) * SROW
                                           + ks * 16 + b_k) * 2;
                uint32_t bf[4];
                ldsm_x4(bf, st + BOFFB + boff);
                #pragma unroll
                for (int mt = 0; mt < 2; ++mt) {
                    #pragma unroll
                    for (int h2 = 0; h2 < 2; ++h2) {
                        mma_f16(acc[mt][nt*2+h2], af[mt], bf[2*h2], bf[2*h2+1]);
                        if (TWOA)
                            mma_f16(acc[mt][nt*2+h2], af2[mt], bf[2*h2], bf[2*h2+1]);
                    }
                }
            }
        }
        __syncthreads();
    }

    #pragma unroll
    for (int mt = 0; mt < 2; ++mt) {
        int r = rowBase + wm * 32 + mt * 16 + (lane >> 2);
        #pragma unroll
        for (int j8 = 0; j8 < 8; ++j8) {
            int cc = colBase + wn * 64 + j8 * 8 + 2 * (lane & 3);
            float v0 = acc[mt][j8][0], v1 = acc[mt][j8][1];
            float v2 = acc[mt][j8][2], v3 = acc[mt][j8][3];
            if (SILU) {
                float a0 = v0 / (1.f + __expf(-v0)) * v1;
                float a1 = v2 / (1.f + __expf(-v2)) * v3;
                Ch[(size_t)r * ldc + (cc >> 1)]       = __float2half_rn(a0);
                Ch[(size_t)(r + 8) * ldc + (cc >> 1)] = __float2half_rn(a1);
            } else if (H16OUT) {
                *(__half2*)(Ch + (size_t)r * ldc + cc) =
                    __half2(__float2half_rn(v0), __float2half_rn(v1));
                *(__half2*)(Ch + (size_t)(r + 8) * ldc + cc) =
                    __half2(__float2half_rn(v2), __float2half_rn(v3));
            } else {
                if (ADDC) {
                    float2 a0 = *(const float2*)(ADDp + (size_t)r * ldc + cc);
                    float2 a1 = *(const float2*)(ADDp + (size_t)(r + 8) * ldc + cc);
                    v0 += a0.x; v1 += a0.y; v2 += a1.x; v3 += a1.y;
                }
                *(float2*)(Cf + (size_t)r * ldc + cc)       = make_float2(v0, v1);
                *(float2*)(Cf + (size_t)(r + 8) * ldc + cc) = make_float2(v2, v3);
            }
        }
    }
}

// ---------------- host launcher ----------------
extern "C" void kernel_launch(void* const* d_in, const int* in_sizes, int n_in,
                              void* d_out, int out_size)
{
    const float* hs    = (const float*)d_in[0];
    const float* resid = (const float*)d_in[1];
    const float* cosp  = (const float*)d_in[2];
    const float* sinp  = (const float*)d_in[3];
    const float* w_qkv = (const float*)d_in[4];
    const float* w_o   = (const float*)d_in[5];
    const float* w_gu  = (const float*)d_in[6];
    const float* w_dn  = (const float*)d_in[7];
    const float* ln1   = (const float*)d_in[8];
    const float* ln2   = (const float*)d_in[9];

    float* out     = (float*)d_out;
    float* mlp_out = out;
    float* res2    = out + (size_t)Tc * Hc;

    float *p_res1, *p_qkv;
    cudaGetSymbolAddress((void**)&p_res1, g_res1);
    cudaGetSymbolAddress((void**)&p_qkv,  g_qkv);
    __nv_bfloat16 *qh,*ql,*kh,*kl;
    cudaGetSymbolAddress((void**)&qh, g_q_hi); cudaGetSymbolAddress((void**)&ql, g_q_lo);
    cudaGetSymbolAddress((void**)&kh, g_k_hi); cudaGetSymbolAddress((void**)&kl, g_k_lo);
    __half *nh1,*nh2,*wqh,*vth,*ath,*n2h,*ach,*woh,*wgh,*wdh;
    cudaGetSymbolAddress((void**)&nh1, g_n_h1);
    cudaGetSymbolAddress((void**)&nh2, g_n_h2);
    cudaGetSymbolAddress((void**)&wqh, g_wqkv_h);
    cudaGetSymbolAddress((void**)&vth, g_vt_h);
    cudaGetSymbolAddress((void**)&ath, g_at_h);
    cudaGetSymbolAddress((void**)&n2h, g_n2_h);
    cudaGetSymbolAddress((void**)&ach, g_ac_h);
    cudaGetSymbolAddress((void**)&woh, g_wo_h);
    cudaGetSymbolAddress((void**)&wgh, g_wgu_h);
    cudaGetSymbolAddress((void**)&wdh, g_wdn_h);

    constexpr int SM1 = 3 * (2 * hk::PL);
    constexpr int SM2 = 3 * (3 * hk::PL);
    cudaFuncSetAttribute(flash_attn_kernel, cudaFuncAttributeMaxDynamicSharedMemorySize, fa::SMEM_SZ);
    cudaFuncSetAttribute(h16_gemm_kernel<true, false,false,false>, cudaFuncAttributeMaxDynamicSharedMemorySize, SM1);
    cudaFuncSetAttribute(h16_gemm_kernel<false,false,false,false>, cudaFuncAttributeMaxDynamicSharedMemorySize, SM1);
    cudaFuncSetAttribute(h16_gemm_kernel<false,false,true, false>, cudaFuncAttributeMaxDynamicSharedMemorySize, SM1);
    cudaFuncSetAttribute(h16_gemm_kernel<false,false,false,true >, cudaFuncAttributeMaxDynamicSharedMemorySize, SM2);

    // weight prep
    transpose_h16_kernel<<<dim3(3*Hc/32, Hc/32), 256>>>(w_qkv, 0, 0, 3*Hc, wqh, 0, Hc, 0);
    transpose_h16_kernel<<<dim3(Hc/32,   Hc/32), 256>>>(w_o,  0, 0, Hc,   woh, 0, Hc, 0);
    transpose_h16_kernel<<<dim3(2*Ic/32, Hc/32), 256>>>(w_gu, 0, 0, 2*Ic, wgh, 0, Hc, Ic);
    transpose_h16_kernel<<<dim3(Hc/32,   Ic/32), 256>>>(w_dn, 0, 0, Hc,   wdh, 0, Ic, 0);

    // 1) res1 + RMSNorm -> fp16 hi/lo duo
    add_rmsnorm_kernel<<<Tc, 256>>>(hs, resid, ln1, p_res1, nh1, nh2, nullptr);

    // 2) qkv = normed @ w_qkv (fp16 2-pass TWOA, fp32 out)
    h16_gemm_kernel<false,false,false,true><<<dim3(3*Hc/128, Tc/128), 256, SM2>>>(
        nh1, nh2, wqh, p_qkv, nullptr, nullptr, Hc, Hc, Hc, 3*Hc);

    // 3) RoPE (scale folded into Q) + V transpose (fp16)
    rope_kernel<<<(Tc*2*NHc*HALFc)/256, 256>>>(p_qkv, cosp, sinp, qh, ql, kh, kl);
    transpose_h16_kernel<<<dim3(HDc/32, Sc/32, Bc*NHc), 256>>>(
        p_qkv + 2*Hc, (long long)Sc*3*Hc, HDc, 3*Hc, vth, (long long)HDc*Sc, Sc, 0);

    // 4) fused flash attention -> ath fp16
    flash_attn_kernel<<<dim3(1, Sc/128, Bc*NHc), 256, fa::SMEM_SZ>>>(
        qh, ql, kh, kl, vth, ath);

    // 5) res2 = attn @ w_o + res1 (fp16 1-pass, into output)
    h16_gemm_kernel<true,false,false,false><<<dim3(Hc/128, Tc/128), 256, SM1>>>(
        ath, nullptr, woh, res2, nullptr, p_res1, Hc, Hc, Hc, Hc);

    // 6) RMSNorm(res2) -> fp16 single plane
    add_rmsnorm_kernel<<<Tc, 256>>>(res2, nullptr, ln2, nullptr, nullptr, nullptr, n2h);

    // 7) ac = silu(gate)*up fused (fp16 1-pass, interleaved weights)
    h16_gemm_kernel<false,false,true,false><<<dim3(2*Ic/128, Tc/128), 256, SM1>>>(
        n2h, nullptr, wgh, nullptr, ach, nullptr, Hc, Hc, Hc, Ic);

    // 8) mlp_out = ac @ w_down (fp16 1-pass, into output)
    h16_gemm_kernel<false,false,false,false><<<dim3(Hc/128, Tc/128), 256, SM1>>>(
        ach, nullptr, wdh, mlp_out, nullptr, nullptr, Ic, Ic, Ic, Hc);
}